// round 1
// baseline (speedup 1.0000x reference)
#include <cuda_runtime.h>
#include <math.h>

#define BB 8
#define TT 1024
#define LLn 4
#define IIn 4
#define HH 768
#define NHEAD 4
#define DH 192
#define NLAY 3
#define NN (TT+LLn+IIn)      /* 1032 */
#define MROWS (BB*NN)        /* 8256 */
#define SPLIT 32

__device__ float g_h [MROWS*HH];
__device__ float g_hw[MROWS*HH];
__device__ float g_es[MROWS*NHEAD];
__device__ float g_ed[MROWS*NHEAD];
__device__ int   g_minL[BB*TT];
__device__ int   g_minI[BB*TT];
__device__ float g_nrm[BB*8];
__device__ float g_m[BB*8*NHEAD];
__device__ float g_s[BB*8*NHEAD];
__device__ float g_alpha[BB*TT*8*NHEAD];
__device__ float g_agg[BB*8*HH];

__device__ __forceinline__ float lrelu(float x){ return x>0.f ? x : 0.2f*x; }

// 8 static in-edges for big node j (0..3 = label j, 4..7 = image j-4)
__device__ __forceinline__ int static_src(int j,int s){
  if (j<LLn){                       // label dst
    if (s<4) return TT+LLn+s;       // 4 images -> label
    if (s<7){ int p=s-4; if(p>=j)p++; return TT+p; }  // 3 other labels
    return TT+j;                    // self
  } else {
    int jj=j-LLn;                   // image dst
    if (s<4) return TT+s;           // 4 labels -> image
    if (s<7){ int p=s-4; if(p>=jj)p++; return TT+LLn+p; } // 3 other images
    return TT+LLn+jj;               // self
  }
}

// ---------------- pack inputs into node state ----------------
__global__ void k_pack(const float* __restrict__ text,const float* __restrict__ lab,
                       const float* __restrict__ img){
  int idx = blockIdx.x*256 + threadIdx.x;
  if (idx >= MROWS*HH) return;
  int c = idx % HH;
  int n = (idx / HH) % NN;
  int b = idx / (NN*HH);
  float v;
  if (n < TT)            v = text[((size_t)b*TT + n)*HH + c];
  else if (n < TT+LLn)   v = lab [((size_t)b*LLn + (n-TT))*HH + c];
  else                   v = img [((size_t)b*IIn + (n-TT-LLn))*HH + c];
  g_h[idx] = v;
}

// ---------------- per-sample label/image norms ----------------
__global__ void k_norm(const float* __restrict__ lab,const float* __restrict__ img){
  int b = blockIdx.x / 8, j = blockIdx.x % 8;
  const float* row = (j<LLn) ? (lab + ((size_t)b*LLn + j)*HH)
                             : (img + ((size_t)b*IIn + (j-LLn))*HH);
  float s = 0.f;
  for (int c=threadIdx.x; c<HH; c+=128){ float v=row[c]; s += v*v; }
  __shared__ float red[128];
  red[threadIdx.x]=s; __syncthreads();
  for (int st=64; st>0; st>>=1){
    if (threadIdx.x<st) red[threadIdx.x]+=red[threadIdx.x+st];
    __syncthreads();
  }
  if (threadIdx.x==0) g_nrm[blockIdx.x] = sqrtf(red[0]);
}

// ---------------- top-k (store excluded argmin) ----------------
__global__ void k_topk(const float* __restrict__ text,const float* __restrict__ lab,
                       const float* __restrict__ img){
  int bt = blockIdx.x;
  int b = bt / TT, t = bt % TT;
  const float* trow = text + ((size_t)b*TT + t)*HH;
  const float* lb = lab + (size_t)b*LLn*HH;
  const float* im = img + (size_t)b*IIn*HH;
  float acc[9];
  #pragma unroll
  for (int i=0;i<9;i++) acc[i]=0.f;
  for (int c=threadIdx.x; c<HH; c+=128){
    float tv = trow[c];
    acc[0] += tv*tv;
    #pragma unroll
    for (int j=0;j<4;j++) acc[1+j] += tv*lb[j*HH+c];
    #pragma unroll
    for (int j=0;j<4;j++) acc[5+j] += tv*im[j*HH+c];
  }
  __shared__ float red[9][4];
  int lane=threadIdx.x&31, w=threadIdx.x>>5;
  #pragma unroll
  for (int i=0;i<9;i++){
    float v=acc[i];
    for (int o=16;o>0;o>>=1) v += __shfl_down_sync(0xffffffffu,v,o);
    if (lane==0) red[i][w]=v;
  }
  __syncthreads();
  if (threadIdx.x==0){
    float tot[9];
    #pragma unroll
    for (int i=0;i<9;i++) tot[i]=red[i][0]+red[i][1]+red[i][2]+red[i][3];
    float tn = sqrtf(tot[0]);
    int amL=0; float mvL=3.4e38f;
    for (int j=0;j<4;j++){
      float den = fmaxf(tn*g_nrm[b*8+j], 1e-8f);
      float s = tot[1+j]/den;
      if (s<mvL){ mvL=s; amL=j; }
    }
    g_minL[bt]=amL;
    int amI=0; float mvI=3.4e38f;
    for (int j=0;j<4;j++){
      float den = fmaxf(tn*g_nrm[b*8+4+j], 1e-8f);
      float s = tot[5+j]/den;
      if (s<mvI){ mvI=s; amI=j; }
    }
    g_minI[bt]=amI;
  }
}

// ---------------- GEMM: g_hw = g_h @ W  (M=8256, N=768, K=768) ----------------
// 128x64 tile, BK=8, 256 threads, 8x4 per-thread microtile.
__global__ void k_gemm(const float* __restrict__ Wm){
  __shared__ float As[8][128];
  __shared__ float Bs[8][64];
  int tid = threadIdx.x;
  int bx = blockIdx.x;            // n tile (0..11)
  int by = blockIdx.y;            // m tile (0..64)
  int trow = tid/16, tcol = tid%16;
  int ar = tid>>1, ac = (tid&1)*4;
  int brow = tid>>5, bcol = (tid&31)*2;
  int grA = by*128 + ar;
  const float* Aptr = g_h + (size_t)grA*HH;
  bool aval = grA < MROWS;
  float acc[8][4];
  #pragma unroll
  for (int i=0;i<8;i++)
    #pragma unroll
    for (int j=0;j<4;j++) acc[i][j]=0.f;

  for (int k0=0; k0<HH; k0+=8){
    float4 av = aval ? *(const float4*)(Aptr + k0 + ac) : make_float4(0.f,0.f,0.f,0.f);
    As[ac+0][ar]=av.x; As[ac+1][ar]=av.y; As[ac+2][ar]=av.z; As[ac+3][ar]=av.w;
    float2 bv = *(const float2*)(Wm + (size_t)(k0+brow)*HH + bx*64 + bcol);
    Bs[brow][bcol]=bv.x; Bs[brow][bcol+1]=bv.y;
    __syncthreads();
    #pragma unroll
    for (int kk=0;kk<8;kk++){
      float a[8], bfr[4];
      *(float4*)&a[0] = *(const float4*)&As[kk][trow*8];
      *(float4*)&a[4] = *(const float4*)&As[kk][trow*8+4];
      *(float4*)&bfr[0] = *(const float4*)&Bs[kk][tcol*4];
      #pragma unroll
      for (int i=0;i<8;i++)
        #pragma unroll
        for (int j=0;j<4;j++) acc[i][j] += a[i]*bfr[j];
    }
    __syncthreads();
  }
  #pragma unroll
  for (int i=0;i<8;i++){
    int gr = by*128 + trow*8 + i;
    if (gr < MROWS){
      float4 v = make_float4(acc[i][0],acc[i][1],acc[i][2],acc[i][3]);
      *(float4*)(g_hw + (size_t)gr*HH + bx*64 + tcol*4) = v;
    }
  }
}

// ---------------- attention scalars es/ed ----------------
__global__ void k_scal(const float* __restrict__ asrc,const float* __restrict__ adst){
  int n = blockIdx.x;
  int head = threadIdx.x>>5, lane = threadIdx.x&31;
  const float* row = g_hw + (size_t)n*HH + head*DH;
  const float* ap = asrc + head*DH;
  const float* dp = adst + head*DH;
  float ss=0.f, sd=0.f;
  for (int d=lane; d<DH; d+=32){ float hv=row[d]; ss+=hv*ap[d]; sd+=hv*dp[d]; }
  for (int o=16;o>0;o>>=1){
    ss += __shfl_down_sync(0xffffffffu,ss,o);
    sd += __shfl_down_sync(0xffffffffu,sd,o);
  }
  if (lane==0){ g_es[n*NHEAD+head]=ss; g_ed[n*NHEAD+head]=sd; }
}

// ---------------- big-node softmax max & sumexp (and zero agg) ----------------
__global__ void k_ms(){
  int b = blockIdx.x>>3, j = blockIdx.x&7;
  int tid = threadIdx.x;
  int jj = (j<LLn)? j : j-LLn;
  int dst = (j<LLn)? (TT+j) : (TT+LLn+jj);
  for (int c=tid;c<HH;c+=256) g_agg[blockIdx.x*HH+c]=0.f;
  float edv[4];
  #pragma unroll
  for (int h=0;h<4;h++) edv[h]=g_ed[(size_t)(b*NN+dst)*NHEAD+h];
  const int* minA = (j<LLn)? (g_minL+b*TT) : (g_minI+b*TT);
  float mx[4]={-3.4e38f,-3.4e38f,-3.4e38f,-3.4e38f};
  for (int t=tid;t<TT;t+=256){
    if (minA[t]!=jj){
      const float* e = g_es + (size_t)(b*NN+t)*NHEAD;
      #pragma unroll
      for (int h=0;h<4;h++) mx[h]=fmaxf(mx[h], lrelu(e[h]+edv[h]));
    }
  }
  if (tid==0){
    #pragma unroll
    for (int s=0;s<8;s++){
      int sr = static_src(j,s);
      const float* e = g_es + (size_t)(b*NN+sr)*NHEAD;
      #pragma unroll
      for (int h=0;h<4;h++) mx[h]=fmaxf(mx[h], lrelu(e[h]+edv[h]));
    }
  }
  __shared__ float red[256][4];
  #pragma unroll
  for (int h=0;h<4;h++) red[tid][h]=mx[h];
  __syncthreads();
  for (int st=128;st>0;st>>=1){
    if (tid<st){
      #pragma unroll
      for (int h=0;h<4;h++) red[tid][h]=fmaxf(red[tid][h],red[tid+st][h]);
    }
    __syncthreads();
  }
  float mv[4];
  #pragma unroll
  for (int h=0;h<4;h++) mv[h]=red[0][h];
  __syncthreads();
  float sm[4]={0.f,0.f,0.f,0.f};
  for (int t=tid;t<TT;t+=256){
    if (minA[t]!=jj){
      const float* e = g_es + (size_t)(b*NN+t)*NHEAD;
      #pragma unroll
      for (int h=0;h<4;h++) sm[h] += __expf(lrelu(e[h]+edv[h])-mv[h]);
    }
  }
  if (tid==0){
    #pragma unroll
    for (int s=0;s<8;s++){
      int sr = static_src(j,s);
      const float* e = g_es + (size_t)(b*NN+sr)*NHEAD;
      #pragma unroll
      for (int h=0;h<4;h++) sm[h] += __expf(lrelu(e[h]+edv[h])-mv[h]);
    }
  }
  #pragma unroll
  for (int h=0;h<4;h++) red[tid][h]=sm[h];
  __syncthreads();
  for (int st=128;st>0;st>>=1){
    if (tid<st){
      #pragma unroll
      for (int h=0;h<4;h++) red[tid][h]+=red[tid+st][h];
    }
    __syncthreads();
  }
  if (tid<4){
    g_m[(b*8+j)*NHEAD+tid]=mv[tid];
    g_s[(b*8+j)*NHEAD+tid]=red[0][tid];
  }
}

// ---------------- dynamic-edge alphas (text -> big nodes) ----------------
__global__ void k_alpha(){
  int idx = blockIdx.x*256 + threadIdx.x;
  if (idx >= BB*TT*8) return;
  int j = idx & 7;
  int t = (idx>>3) % TT;
  int b = idx / (TT*8);
  int jj = (j<LLn)? j : j-LLn;
  int mem = (j<LLn)? (g_minL[b*TT+t]!=jj) : (g_minI[b*TT+t]!=jj);
  float* outp = g_alpha + (size_t)idx*NHEAD;
  if (!mem){
    #pragma unroll
    for (int h=0;h<4;h++) outp[h]=0.f;
    return;
  }
  int dst = (j<LLn)? (TT+j) : (TT+LLn+jj);
  const float* e  = g_es + (size_t)(b*NN+t)*NHEAD;
  const float* ed = g_ed + (size_t)(b*NN+dst)*NHEAD;
  const float* mp = g_m + (b*8+j)*NHEAD;
  const float* sp = g_s + (b*8+j)*NHEAD;
  #pragma unroll
  for (int h=0;h<4;h++)
    outp[h] = __expf(lrelu(e[h]+ed[h])-mp[h]) / sp[h];
}

// ---------------- big-node weighted aggregation ----------------
__global__ void k_agg(){
  int blk = blockIdx.x;
  int sp = blk % SPLIT;
  int j  = (blk/SPLIT) & 7;
  int b  = blk / (SPLIT*8);
  int tid = threadIdx.x;
  int jj = (j<LLn)? j : j-LLn;
  int dst = (j<LLn)? (TT+j) : (TT+LLn+jj);
  const int* minA = (j<LLn)? (g_minL+b*TT) : (g_minI+b*TT);
  int c0=tid, c1=tid+256, c2=tid+512;
  int h0=c0/DH, h1=c1/DH, h2=c2/DH;
  float a0=0.f,a1=0.f,a2=0.f;
  int t0 = sp*(TT/SPLIT), t1 = t0 + (TT/SPLIT);
  for (int t=t0;t<t1;t++){
    if (minA[t]==jj) continue;
    const float* al = g_alpha + (size_t)((b*TT+t)*8+j)*NHEAD;
    float w0=al[h0], w1=al[h1], w2=al[h2];
    const float* hr = g_hw + (size_t)(b*NN+t)*HH;
    a0 += w0*hr[c0]; a1 += w1*hr[c1]; a2 += w2*hr[c2];
  }
  if (sp==0){
    __shared__ float sal[8][4];
    __shared__ int ssrc[8];
    if (tid<32){
      int s=tid>>2, h=tid&3;
      int sr = static_src(j,s);
      if (h==0) ssrc[s]=sr;
      float e = lrelu(g_es[(size_t)(b*NN+sr)*NHEAD+h] + g_ed[(size_t)(b*NN+dst)*NHEAD+h]);
      sal[s][h] = __expf(e - g_m[(b*8+j)*NHEAD+h]) / g_s[(b*8+j)*NHEAD+h];
    }
    __syncthreads();
    #pragma unroll
    for (int s=0;s<8;s++){
      const float* hr = g_hw + (size_t)(b*NN+ssrc[s])*HH;
      a0 += sal[s][h0]*hr[c0]; a1 += sal[s][h1]*hr[c1]; a2 += sal[s][h2]*hr[c2];
    }
  }
  atomicAdd(&g_agg[(b*8+j)*HH+c0], a0);
  atomicAdd(&g_agg[(b*8+j)*HH+c1], a1);
  atomicAdd(&g_agg[(b*8+j)*HH+c2], a2);
}

// ---------------- big-node epilogue: bias+relu+residual+LN ----------------
__global__ void k_big(const float* __restrict__ bias,const float* __restrict__ lng,
                      const float* __restrict__ lnb){
  int b = blockIdx.x>>3, j = blockIdx.x&7;
  int jj = (j<LLn)? j : j-LLn;
  int node = (j<LLn)? (TT+j) : (TT+LLn+jj);
  int tid = threadIdx.x;
  size_t row = (size_t)(b*NN+node)*HH;
  float v[3]; float s=0.f, sq=0.f;
  #pragma unroll
  for (int r=0;r<3;r++){
    int c = tid + 256*r;
    float o = g_agg[(b*8+j)*HH+c] + bias[c];
    o = fmaxf(o, 0.f);
    float y = o + g_h[row+c];
    v[r]=y; s+=y; sq+=y*y;
  }
  __shared__ float rs[256], rq[256];
  rs[tid]=s; rq[tid]=sq; __syncthreads();
  for (int st=128;st>0;st>>=1){
    if (tid<st){ rs[tid]+=rs[tid+st]; rq[tid]+=rq[tid+st]; }
    __syncthreads();
  }
  float mu = rs[0]*(1.f/HH);
  float var = rq[0]*(1.f/HH) - mu*mu;
  float rstd = rsqrtf(var + 1e-5f);
  #pragma unroll
  for (int r=0;r<3;r++){
    int c = tid + 256*r;
    g_h[row+c] = (v[r]-mu)*rstd*lng[c] + lnb[c];
  }
}

// ---------------- text-node: full fused attention + epilogue ----------------
__global__ void k_text(const float* __restrict__ bias,const float* __restrict__ lng,
                       const float* __restrict__ lnb){
  int bt = blockIdx.x;
  int b = bt/TT, t = bt%TT;
  int tid = threadIdx.x;
  __shared__ int ssrc[9];
  __shared__ int snum;
  __shared__ float sal[9][4];
  if (tid==0){
    int n=0;
    ssrc[n++]=t;
    if (t>0)    ssrc[n++]=t-1;
    if (t<TT-1) ssrc[n++]=t+1;
    int ml=g_minL[bt], mi=g_minI[bt];
    #pragma unroll
    for (int j2=0;j2<4;j2++) if (j2!=ml) ssrc[n++]=TT+j2;
    #pragma unroll
    for (int j2=0;j2<4;j2++) if (j2!=mi) ssrc[n++]=TT+LLn+j2;
    snum=n;
  }
  __syncthreads();
  int ns = snum;
  if (tid<4){
    float ed = g_ed[(size_t)(b*NN+t)*NHEAD + tid];
    float ev[9]; float mxv=-3.4e38f;
    for (int e=0;e<ns;e++){
      float x = lrelu(g_es[(size_t)(b*NN+ssrc[e])*NHEAD + tid] + ed);
      ev[e]=x; mxv=fmaxf(mxv,x);
    }
    float sm=0.f;
    for (int e=0;e<ns;e++){ float w=__expf(ev[e]-mxv); ev[e]=w; sm+=w; }
    float inv = 1.f/sm;
    for (int e=0;e<ns;e++) sal[e][tid]=ev[e]*inv;
  }
  __syncthreads();
  size_t row = (size_t)(b*NN+t)*HH;
  float v[3]; float s=0.f, sq=0.f;
  #pragma unroll
  for (int r=0;r<3;r++){
    int c = tid + 256*r;
    int hd = c/DH;
    float a = 0.f;
    for (int e=0;e<ns;e++)
      a += sal[e][hd] * g_hw[(size_t)(b*NN+ssrc[e])*HH + c];
    float o = fmaxf(a + bias[c], 0.f);
    float y = o + g_h[row+c];
    v[r]=y; s+=y; sq+=y*y;
  }
  __shared__ float rs[256], rq[256];
  rs[tid]=s; rq[tid]=sq; __syncthreads();
  for (int st=128;st>0;st>>=1){
    if (tid<st){ rs[tid]+=rs[tid+st]; rq[tid]+=rq[tid+st]; }
    __syncthreads();
  }
  float mu = rs[0]*(1.f/HH);
  float var = rq[0]*(1.f/HH) - mu*mu;
  float rstd = rsqrtf(var + 1e-5f);
  #pragma unroll
  for (int r=0;r<3;r++){
    int c = tid + 256*r;
    g_h[row+c] = (v[r]-mu)*rstd*lng[c] + lnb[c];
  }
}

// ---------------- output copy ----------------
__global__ void k_out(float* __restrict__ out){
  int idx = blockIdx.x*256 + threadIdx.x;
  if (idx >= BB*TT*HH) return;
  int c = idx % HH;
  int t = (idx/HH) % TT;
  int b = idx / (TT*HH);
  out[idx] = g_h[(size_t)(b*NN+t)*HH + c];
}

extern "C" void kernel_launch(void* const* d_in, const int* in_sizes, int n_in,
                              void* d_out, int out_size) {
  const float* text = (const float*)d_in[0];
  const float* lab  = (const float*)d_in[1];
  const float* img  = (const float*)d_in[2];
  const float* W    = (const float*)d_in[3];
  const float* asrc = (const float*)d_in[4];
  const float* adst = (const float*)d_in[5];
  const float* bias = (const float*)d_in[6];
  const float* lng  = (const float*)d_in[7];
  const float* lnb  = (const float*)d_in[8];
  float* out = (float*)d_out;

  k_pack<<<(MROWS*HH+255)/256, 256>>>(text, lab, img);
  k_norm<<<BB*8, 128>>>(lab, img);
  k_topk<<<BB*TT, 128>>>(text, lab, img);

  for (int l=0; l<NLAY; l++){
    const float* Wl = W + (size_t)l*HH*HH;
    k_gemm<<<dim3(12,65), 256>>>(Wl);
    k_scal<<<MROWS, 128>>>(asrc + l*NHEAD*DH, adst + l*NHEAD*DH);
    k_ms<<<BB*8, 256>>>();
    k_alpha<<<(BB*TT*8+255)/256, 256>>>();
    k_text<<<BB*TT, 256>>>(bias + l*HH, lng + l*HH, lnb + l*HH);
    k_agg<<<BB*8*SPLIT, 256>>>();
    k_big<<<BB*8, 256>>>(bias + l*HH, lng + l*HH, lnb + l*HH);
  }
  k_out<<<(BB*TT*HH+255)/256, 256>>>(out);
}

// round 4
// speedup vs baseline: 1.4467x; 1.4467x over previous
#include <cuda_runtime.h>
#include <cuda_bf16.h>
#include <math.h>
#include <cstdint>

#define BB 8
#define TT 1024
#define LLn 4
#define IIn 4
#define HH 768
#define NHEAD 4
#define DH 192
#define NLAY 3
#define NN (TT+LLn+IIn)      /* 1032 */
#define MROWS (BB*NN)        /* 8256 */
#define SPLIT 32

__device__ float g_h [MROWS*HH];
__device__ float g_hw[MROWS*HH];
__device__ float g_es[MROWS*NHEAD];
__device__ float g_ed[MROWS*NHEAD];
__device__ int   g_minL[BB*TT];
__device__ int   g_minI[BB*TT];
__device__ float g_nrm[BB*8];
__device__ float g_m[BB*8*NHEAD];
__device__ float g_s[BB*8*NHEAD];
__device__ float g_alpha[BB*TT*8*NHEAD];
__device__ float g_agg[BB*8*HH];

// bf16 split operands for tensor-core GEMM
__device__ __nv_bfloat16 g_hh[MROWS*HH];
__device__ __nv_bfloat16 g_hl[MROWS*HH];
__device__ __nv_bfloat16 g_wh[NLAY*HH*HH];   // transposed: [n][k]
__device__ __nv_bfloat16 g_wl[NLAY*HH*HH];

__device__ __forceinline__ float lrelu(float x){ return x>0.f ? x : 0.2f*x; }

// ---------------- pack inputs into node state ----------------
__global__ void k_pack(const float* __restrict__ text,const float* __restrict__ lab,
                       const float* __restrict__ img){
  int idx = blockIdx.x*256 + threadIdx.x;
  if (idx >= MROWS*HH) return;
  int c = idx % HH;
  int n = (idx / HH) % NN;
  int b = idx / (NN*HH);
  float v;
  if (n < TT)            v = text[((size_t)b*TT + n)*HH + c];
  else if (n < TT+LLn)   v = lab [((size_t)b*LLn + (n-TT))*HH + c];
  else                   v = img [((size_t)b*IIn + (n-TT-LLn))*HH + c];
  g_h[idx] = v;
}

// ---------------- convert weights: transpose + bf16 split (all layers) ----------------
__global__ void k_cvtW(const float* __restrict__ W){
  __shared__ float tile[32][33];
  int l = blockIdx.z;
  int n0 = blockIdx.x*32, k0 = blockIdx.y*32;
  const float* Wl = W + (size_t)l*HH*HH;
  tile[threadIdx.y][threadIdx.x] = Wl[(size_t)(k0+threadIdx.y)*HH + n0+threadIdx.x];
  __syncthreads();
  float x = tile[threadIdx.x][threadIdx.y];      // = Wl[k0+tx][n0+ty]
  __nv_bfloat16 hi = __float2bfloat16(x);
  __nv_bfloat16 lo = __float2bfloat16(x - __bfloat162float(hi));
  size_t o = (size_t)l*HH*HH + (size_t)(n0+threadIdx.y)*HH + (k0+threadIdx.x);
  g_wh[o] = hi; g_wl[o] = lo;
}

// ---------------- convert activations: bf16 split ----------------
__global__ void k_cvtH(){
  int idx = blockIdx.x*256 + threadIdx.x;
  if (idx >= MROWS*HH) return;
  float x = g_h[idx];
  __nv_bfloat16 hi = __float2bfloat16(x);
  g_hh[idx] = hi;
  g_hl[idx] = __float2bfloat16(x - __bfloat162float(hi));
}

// ---------------- per-sample label/image norms ----------------
__global__ void k_norm(const float* __restrict__ lab,const float* __restrict__ img){
  int b = blockIdx.x / 8, j = blockIdx.x % 8;
  const float* row = (j<LLn) ? (lab + ((size_t)b*LLn + j)*HH)
                             : (img + ((size_t)b*IIn + (j-LLn))*HH);
  float s = 0.f;
  for (int c=threadIdx.x; c<HH; c+=128){ float v=row[c]; s += v*v; }
  __shared__ float red[128];
  red[threadIdx.x]=s; __syncthreads();
  for (int st=64; st>0; st>>=1){
    if (threadIdx.x<st) red[threadIdx.x]+=red[threadIdx.x+st];
    __syncthreads();
  }
  if (threadIdx.x==0) g_nrm[blockIdx.x] = sqrtf(red[0]);
}

// ---------------- top-k (store excluded argmin) ----------------
__global__ void k_topk(const float* __restrict__ text,const float* __restrict__ lab,
                       const float* __restrict__ img){
  int bt = blockIdx.x;
  int b = bt / TT, t = bt % TT;
  const float* trow = text + ((size_t)b*TT + t)*HH;
  const float* lb = lab + (size_t)b*LLn*HH;
  const float* im = img + (size_t)b*IIn*HH;
  float acc[9];
  #pragma unroll
  for (int i=0;i<9;i++) acc[i]=0.f;
  for (int c=threadIdx.x; c<HH; c+=128){
    float tv = trow[c];
    acc[0] += tv*tv;
    #pragma unroll
    for (int j=0;j<4;j++) acc[1+j] += tv*lb[j*HH+c];
    #pragma unroll
    for (int j=0;j<4;j++) acc[5+j] += tv*im[j*HH+c];
  }
  __shared__ float red[9][4];
  int lane=threadIdx.x&31, w=threadIdx.x>>5;
  #pragma unroll
  for (int i=0;i<9;i++){
    float v=acc[i];
    for (int o=16;o>0;o>>=1) v += __shfl_down_sync(0xffffffffu,v,o);
    if (lane==0) red[i][w]=v;
  }
  __syncthreads();
  if (threadIdx.x==0){
    float tot[9];
    #pragma unroll
    for (int i=0;i<9;i++) tot[i]=red[i][0]+red[i][1]+red[i][2]+red[i][3];
    float tn = sqrtf(tot[0]);
    int amL=0; float mvL=3.4e38f;
    for (int j=0;j<4;j++){
      float den = fmaxf(tn*g_nrm[b*8+j], 1e-8f);
      float s = tot[1+j]/den;
      if (s<mvL){ mvL=s; amL=j; }
    }
    g_minL[bt]=amL;
    int amI=0; float mvI=3.4e38f;
    for (int j=0;j<4;j++){
      float den = fmaxf(tn*g_nrm[b*8+4+j], 1e-8f);
      float s = tot[5+j]/den;
      if (s<mvI){ mvI=s; amI=j; }
    }
    g_minI[bt]=amI;
  }
}

// ======================= HMMA GEMM (mma.sync bf16, 3-term split) =======================
// g_hw = g_h @ W[l].  CTA tile 128x128, k-step 32, double-buffered cp.async.
// SMEM rows padded to 40 bf16 (80B) -> conflict-free ldmatrix (granule 5r mod 8).
#define APAD 40
#define STAGE_B (128*APAD)      /* elements per buffer */

__device__ __forceinline__ uint32_t smem_u32(const void* p){
  return (uint32_t)__cvta_generic_to_shared(p);
}
__device__ __forceinline__ void cp16(uint32_t dst, const void* src){
  asm volatile("cp.async.cg.shared.global [%0], [%1], 16;" :: "r"(dst), "l"(src));
}
__device__ __forceinline__ void cp_commit(){ asm volatile("cp.async.commit_group;"); }
__device__ __forceinline__ void cp_wait1(){ asm volatile("cp.async.wait_group 1;"); }
__device__ __forceinline__ void cp_wait0(){ asm volatile("cp.async.wait_group 0;"); }
__device__ __forceinline__ void ldmx4(uint32_t a, uint32_t& r0, uint32_t& r1, uint32_t& r2, uint32_t& r3){
  asm volatile("ldmatrix.sync.aligned.m8n8.x4.shared.b16 {%0,%1,%2,%3}, [%4];"
    : "=r"(r0), "=r"(r1), "=r"(r2), "=r"(r3) : "r"(a));
}
__device__ __forceinline__ void mma16816(float* d, const uint32_t* a, uint32_t b0, uint32_t b1){
  asm volatile(
    "mma.sync.aligned.m16n8k16.row.col.f32.bf16.bf16.f32 "
    "{%0,%1,%2,%3}, {%4,%5,%6,%7}, {%8,%9}, {%0,%1,%2,%3};"
    : "+f"(d[0]), "+f"(d[1]), "+f"(d[2]), "+f"(d[3])
    : "r"(a[0]), "r"(a[1]), "r"(a[2]), "r"(a[3]), "r"(b0), "r"(b1));
}

__global__ void __launch_bounds__(256,2) k_gemm_mma(int layer){
  __shared__ __nv_bfloat16 As[2][STAGE_B];
  __shared__ __nv_bfloat16 Bs[2][STAGE_B];

  int tid = threadIdx.x;
  int wid = tid >> 5, lane = tid & 31;
  int wm = wid & 3, wn = wid >> 2;        // warp tile: rows wm*32, cols wn*64
  int bx = blockIdx.x;                     // n tile (0..5)
  int by = blockIdx.y;                     // m tile (0..64)

  const __nv_bfloat16* wH = g_wh + (size_t)layer*HH*HH;
  const __nv_bfloat16* wL = g_wl + (size_t)layer*HH*HH;

  // cp.async load indices: idx = tid + 256*i -> row idx>>2, 16B-chunk idx&3
  int lr0 = tid >> 2,        lc0 = (tid & 3) * 8;
  int lr1 = (tid+256) >> 2,  lc1 = lc0;
  int am0 = by*128 + lr0; if (am0 >= MROWS) am0 = MROWS-1;
  int am1 = by*128 + lr1; if (am1 >= MROWS) am1 = MROWS-1;
  int bn0 = bx*128 + lr0;
  int bn1 = bx*128 + lr1;
  uint32_t sA = smem_u32(&As[0][0]);
  uint32_t sB = smem_u32(&Bs[0][0]);
  uint32_t dA0 = sA + (uint32_t)(lr0*APAD + lc0)*2;
  uint32_t dA1 = sA + (uint32_t)(lr1*APAD + lc1)*2;
  uint32_t dB0 = sB + (uint32_t)(lr0*APAD + lc0)*2;
  uint32_t dB1 = sB + (uint32_t)(lr1*APAD + lc1)*2;

  // ldmatrix per-thread address components
  uint32_t aRow = (uint32_t)(wm*32 + ((lane>>3)&1)*8 + (lane&7));  // + mt*16
  uint32_t aCol = (uint32_t)(((lane>>4)&1)*8);                     // + kk
  uint32_t bRow = (uint32_t)(wn*64 + ((lane>>4)&1)*8 + (lane&7));  // + nt*16
  uint32_t bCol = (uint32_t)(((lane>>3)&1)*8);                     // + kk

  float acc[2][8][4];
  #pragma unroll
  for (int i=0;i<2;i++)
    #pragma unroll
    for (int j=0;j<8;j++)
      #pragma unroll
      for (int k=0;k<4;k++) acc[i][j][k]=0.f;

  const int NSTAGE = 72;   // 3 terms * 24 k-steps
  // stage loader
  auto issue = [&](int s){
    int term = s / 24;
    int k0 = (s % 24) * 32;
    int buf = s & 1;
    const __nv_bfloat16* aS = (term < 2) ? g_hh : g_hl;
    const __nv_bfloat16* bS = (term == 1) ? wL : wH;
    uint32_t off = (uint32_t)(buf * STAGE_B) * 2;
    cp16(dA0 + off, aS + (size_t)am0*HH + k0 + lc0);
    cp16(dA1 + off, aS + (size_t)am1*HH + k0 + lc1);
    cp16(dB0 + off, bS + (size_t)bn0*HH + k0 + lc0);
    cp16(dB1 + off, bS + (size_t)bn1*HH + k0 + lc1);
    cp_commit();
  };

  issue(0);
  for (int s = 0; s < NSTAGE; s++){
    if (s+1 < NSTAGE){ issue(s+1); cp_wait1(); }
    else cp_wait0();
    __syncthreads();
    int buf = s & 1;
    uint32_t aBase = sA + (uint32_t)(buf*STAGE_B)*2;
    uint32_t bBase = sB + (uint32_t)(buf*STAGE_B)*2;
    #pragma unroll
    for (int kk = 0; kk < 32; kk += 16){
      uint32_t a[2][4], b[4][4];
      #pragma unroll
      for (int mt=0; mt<2; mt++){
        uint32_t ad = aBase + ((aRow + mt*16)*APAD + aCol + kk)*2;
        ldmx4(ad, a[mt][0], a[mt][1], a[mt][2], a[mt][3]);
      }
      #pragma unroll
      for (int nt=0; nt<4; nt++){
        uint32_t bd = bBase + ((bRow + nt*16)*APAD + bCol + kk)*2;
        ldmx4(bd, b[nt][0], b[nt][1], b[nt][2], b[nt][3]);
      }
      #pragma unroll
      for (int mt=0; mt<2; mt++)
        #pragma unroll
        for (int n=0; n<8; n++){
          int nt = n >> 1, pr = n & 1;
          mma16816(acc[mt][n], a[mt], b[nt][pr*2], b[nt][pr*2+1]);
        }
    }
    __syncthreads();
  }

  // epilogue: write accumulators to g_hw
  #pragma unroll
  for (int mt=0; mt<2; mt++){
    int r0 = by*128 + wm*32 + mt*16 + (lane>>2);
    #pragma unroll
    for (int n=0; n<8; n++){
      int c0 = bx*128 + wn*64 + n*8 + (lane&3)*2;
      if (r0 < MROWS)
        *(float2*)(g_hw + (size_t)r0*HH + c0) = make_float2(acc[mt][n][0], acc[mt][n][1]);
      if (r0+8 < MROWS)
        *(float2*)(g_hw + (size_t)(r0+8)*HH + c0) = make_float2(acc[mt][n][2], acc[mt][n][3]);
    }
  }
}

// ---------------- attention scalars es/ed ----------------
__global__ void k_scal(const float* __restrict__ asrc,const float* __restrict__ adst){
  int n = blockIdx.x;
  int head = threadIdx.x>>5, lane = threadIdx.x&31;
  const float* row = g_hw + (size_t)n*HH + head*DH;
  const float* ap = asrc + head*DH;
  const float* dp = adst + head*DH;
  float ss=0.f, sd=0.f;
  for (int d=lane; d<DH; d+=32){ float hv=row[d]; ss+=hv*ap[d]; sd+=hv*dp[d]; }
  for (int o=16;o>0;o>>=1){
    ss += __shfl_down_sync(0xffffffffu,ss,o);
    sd += __shfl_down_sync(0xffffffffu,sd,o);
  }
  if (lane==0){ g_es[n*NHEAD+head]=ss; g_ed[n*NHEAD+head]=sd; }
}

// 8 static in-edges for big node j (0..3 = label j, 4..7 = image j-4)
__device__ __forceinline__ int static_src(int j,int s){
  if (j<LLn){
    if (s<4) return TT+LLn+s;
    if (s<7){ int p=s-4; if(p>=j)p++; return TT+p; }
    return TT+j;
  } else {
    int jj=j-LLn;
    if (s<4) return TT+s;
    if (s<7){ int p=s-4; if(p>=jj)p++; return TT+LLn+p; }
    return TT+LLn+jj;
  }
}

// ---------------- big-node softmax max & sumexp (and zero agg) ----------------
__global__ void k_ms(){
  int b = blockIdx.x>>3, j = blockIdx.x&7;
  int tid = threadIdx.x;
  int jj = (j<LLn)? j : j-LLn;
  int dst = (j<LLn)? (TT+j) : (TT+LLn+jj);
  for (int c=tid;c<HH;c+=256) g_agg[blockIdx.x*HH+c]=0.f;
  float edv[4];
  #pragma unroll
  for (int h=0;h<4;h++) edv[h]=g_ed[(size_t)(b*NN+dst)*NHEAD+h];
  const int* minA = (j<LLn)? (g_minL+b*TT) : (g_minI+b*TT);
  float mx[4]={-3.4e38f,-3.4e38f,-3.4e38f,-3.4e38f};
  for (int t=tid;t<TT;t+=256){
    if (minA[t]!=jj){
      const float* e = g_es + (size_t)(b*NN+t)*NHEAD;
      #pragma unroll
      for (int h=0;h<4;h++) mx[h]=fmaxf(mx[h], lrelu(e[h]+edv[h]));
    }
  }
  if (tid==0){
    #pragma unroll
    for (int s=0;s<8;s++){
      int sr = static_src(j,s);
      const float* e = g_es + (size_t)(b*NN+sr)*NHEAD;
      #pragma unroll
      for (int h=0;h<4;h++) mx[h]=fmaxf(mx[h], lrelu(e[h]+edv[h]));
    }
  }
  __shared__ float red[256][4];
  #pragma unroll
  for (int h=0;h<4;h++) red[tid][h]=mx[h];
  __syncthreads();
  for (int st=128;st>0;st>>=1){
    if (tid<st){
      #pragma unroll
      for (int h=0;h<4;h++) red[tid][h]=fmaxf(red[tid][h],red[tid+st][h]);
    }
    __syncthreads();
  }
  float mv[4];
  #pragma unroll
  for (int h=0;h<4;h++) mv[h]=red[0][h];
  __syncthreads();
  float sm[4]={0.f,0.f,0.f,0.f};
  for (int t=tid;t<TT;t+=256){
    if (minA[t]!=jj){
      const float* e = g_es + (size_t)(b*NN+t)*NHEAD;
      #pragma unroll
      for (int h=0;h<4;h++) sm[h] += __expf(lrelu(e[h]+edv[h])-mv[h]);
    }
  }
  if (tid==0){
    #pragma unroll
    for (int s=0;s<8;s++){
      int sr = static_src(j,s);
      const float* e = g_es + (size_t)(b*NN+sr)*NHEAD;
      #pragma unroll
      for (int h=0;h<4;h++) sm[h] += __expf(lrelu(e[h]+edv[h])-mv[h]);
    }
  }
  #pragma unroll
  for (int h=0;h<4;h++) red[tid][h]=sm[h];
  __syncthreads();
  for (int st=128;st>0;st>>=1){
    if (tid<st){
      #pragma unroll
      for (int h=0;h<4;h++) red[tid][h]+=red[tid+st][h];
    }
    __syncthreads();
  }
  if (tid<4){
    g_m[(b*8+j)*NHEAD+tid]=mv[tid];
    g_s[(b*8+j)*NHEAD+tid]=red[0][tid];
  }
}

// ---------------- dynamic-edge alphas (text -> big nodes) ----------------
__global__ void k_alpha(){
  int idx = blockIdx.x*256 + threadIdx.x;
  if (idx >= BB*TT*8) return;
  int j = idx & 7;
  int t = (idx>>3) % TT;
  int b = idx / (TT*8);
  int jj = (j<LLn)? j : j-LLn;
  int mem = (j<LLn)? (g_minL[b*TT+t]!=jj) : (g_minI[b*TT+t]!=jj);
  float* outp = g_alpha + (size_t)idx*NHEAD;
  if (!mem){
    #pragma unroll
    for (int h=0;h<4;h++) outp[h]=0.f;
    return;
  }
  int dst = (j<LLn)? (TT+j) : (TT+LLn+jj);
  const float* e  = g_es + (size_t)(b*NN+t)*NHEAD;
  const float* ed = g_ed + (size_t)(b*NN+dst)*NHEAD;
  const float* mp = g_m + (b*8+j)*NHEAD;
  const float* sp = g_s + (b*8+j)*NHEAD;
  #pragma unroll
  for (int h=0;h<4;h++)
    outp[h] = __expf(lrelu(e[h]+ed[h])-mp[h]) / sp[h];
}

// ---------------- big-node weighted aggregation ----------------
__global__ void k_agg(){
  int blk = blockIdx.x;
  int sp = blk % SPLIT;
  int j  = (blk/SPLIT) & 7;
  int b  = blk / (SPLIT*8);
  int tid = threadIdx.x;
  int jj = (j<LLn)? j : j-LLn;
  int dst = (j<LLn)? (TT+j) : (TT+LLn+jj);
  const int* minA = (j<LLn)? (g_minL+b*TT) : (g_minI+b*TT);
  int c0=tid, c1=tid+256, c2=tid+512;
  int h0=c0/DH, h1=c1/DH, h2=c2/DH;
  float a0=0.f,a1=0.f,a2=0.f;
  int t0 = sp*(TT/SPLIT), t1 = t0 + (TT/SPLIT);
  for (int t=t0;t<t1;t++){
    if (minA[t]==jj) continue;
    const float* al = g_alpha + (size_t)((b*TT+t)*8+j)*NHEAD;
    float w0=al[h0], w1=al[h1], w2=al[h2];
    const float* hr = g_hw + (size_t)(b*NN+t)*HH;
    a0 += w0*hr[c0]; a1 += w1*hr[c1]; a2 += w2*hr[c2];
  }
  if (sp==0){
    __shared__ float sal[8][4];
    __shared__ int ssrc[8];
    if (tid<32){
      int s=tid>>2, h=tid&3;
      int sr = static_src(j,s);
      if (h==0) ssrc[s]=sr;
      float e = lrelu(g_es[(size_t)(b*NN+sr)*NHEAD+h] + g_ed[(size_t)(b*NN+dst)*NHEAD+h]);
      sal[s][h] = __expf(e - g_m[(b*8+j)*NHEAD+h]) / g_s[(b*8+j)*NHEAD+h];
    }
    __syncthreads();
    #pragma unroll
    for (int s=0;s<8;s++){
      const float* hr = g_hw + (size_t)(b*NN+ssrc[s])*HH;
      a0 += sal[s][h0]*hr[c0]; a1 += sal[s][h1]*hr[c1]; a2 += sal[s][h2]*hr[c2];
    }
  }
  atomicAdd(&g_agg[(b*8+j)*HH+c0], a0);
  atomicAdd(&g_agg[(b*8+j)*HH+c1], a1);
  atomicAdd(&g_agg[(b*8+j)*HH+c2], a2);
}

// ---------------- big-node epilogue: bias+relu+residual+LN ----------------
__global__ void k_big(const float* __restrict__ bias,const float* __restrict__ lng,
                      const float* __restrict__ lnb){
  int b = blockIdx.x>>3, j = blockIdx.x&7;
  int jj = (j<LLn)? j : j-LLn;
  int node = (j<LLn)? (TT+j) : (TT+LLn+jj);
  int tid = threadIdx.x;
  size_t row = (size_t)(b*NN+node)*HH;
  float v[3]; float s=0.f, sq=0.f;
  #pragma unroll
  for (int r=0;r<3;r++){
    int c = tid + 256*r;
    float o = g_agg[(b*8+j)*HH+c] + bias[c];
    o = fmaxf(o, 0.f);
    float y = o + g_h[row+c];
    v[r]=y; s+=y; sq+=y*y;
  }
  __shared__ float rs[256], rq[256];
  rs[tid]=s; rq[tid]=sq; __syncthreads();
  for (int st=128;st>0;st>>=1){
    if (tid<st){ rs[tid]+=rs[tid+st]; rq[tid]+=rq[tid+st]; }
    __syncthreads();
  }
  float mu = rs[0]*(1.f/HH);
  float var = rq[0]*(1.f/HH) - mu*mu;
  float rstd = rsqrtf(var + 1e-5f);
  #pragma unroll
  for (int r=0;r<3;r++){
    int c = tid + 256*r;
    g_h[row+c] = (v[r]-mu)*rstd*lng[c] + lnb[c];
  }
}

// ---------------- text-node: full fused attention + epilogue ----------------
__global__ void k_text(const float* __restrict__ bias,const float* __restrict__ lng,
                       const float* __restrict__ lnb){
  int bt = blockIdx.x;
  int b = bt/TT, t = bt%TT;
  int tid = threadIdx.x;
  __shared__ int ssrc[9];
  __shared__ int snum;
  __shared__ float sal[9][4];
  if (tid==0){
    int n=0;
    ssrc[n++]=t;
    if (t>0)    ssrc[n++]=t-1;
    if (t<TT-1) ssrc[n++]=t+1;
    int ml=g_minL[bt], mi=g_minI[bt];
    #pragma unroll
    for (int j2=0;j2<4;j2++) if (j2!=ml) ssrc[n++]=TT+j2;
    #pragma unroll
    for (int j2=0;j2<4;j2++) if (j2!=mi) ssrc[n++]=TT+LLn+j2;
    snum=n;
  }
  __syncthreads();
  int ns = snum;
  if (tid<4){
    float ed = g_ed[(size_t)(b*NN+t)*NHEAD + tid];
    float ev[9]; float mxv=-3.4e38f;
    for (int e=0;e<ns;e++){
      float x = lrelu(g_es[(size_t)(b*NN+ssrc[e])*NHEAD + tid] + ed);
      ev[e]=x; mxv=fmaxf(mxv,x);
    }
    float sm=0.f;
    for (int e=0;e<ns;e++){ float w=__expf(ev[e]-mxv); ev[e]=w; sm+=w; }
    float inv = 1.f/sm;
    for (int e=0;e<ns;e++) sal[e][tid]=ev[e]*inv;
  }
  __syncthreads();
  size_t row = (size_t)(b*NN+t)*HH;
  float v[3]; float s=0.f, sq=0.f;
  #pragma unroll
  for (int r=0;r<3;r++){
    int c = tid + 256*r;
    int hd = c/DH;
    float a = 0.f;
    for (int e=0;e<ns;e++)
      a += sal[e][hd] * g_hw[(size_t)(b*NN+ssrc[e])*HH + c];
    float o = fmaxf(a + bias[c], 0.f);
    float y = o + g_h[row+c];
    v[r]=y; s+=y; sq+=y*y;
  }
  __shared__ float rs[256], rq[256];
  rs[tid]=s; rq[tid]=sq; __syncthreads();
  for (int st=128;st>0;st>>=1){
    if (tid<st){ rs[tid]+=rs[tid+st]; rq[tid]+=rq[tid+st]; }
    __syncthreads();
  }
  float mu = rs[0]*(1.f/HH);
  float var = rq[0]*(1.f/HH) - mu*mu;
  float rstd = rsqrtf(var + 1e-5f);
  #pragma unroll
  for (int r=0;r<3;r++){
    int c = tid + 256*r;
    g_h[row+c] = (v[r]-mu)*rstd*lng[c] + lnb[c];
  }
}

// ---------------- output copy ----------------
__global__ void k_out(float* __restrict__ out){
  int idx = blockIdx.x*256 + threadIdx.x;
  if (idx >= BB*TT*HH) return;
  int c = idx % HH;
  int t = (idx/HH) % TT;
  int b = idx / (TT*HH);
  out[idx] = g_h[(size_t)(b*NN+t)*HH + c];
}

extern "C" void kernel_launch(void* const* d_in, const int* in_sizes, int n_in,
                              void* d_out, int out_size) {
  const float* text = (const float*)d_in[0];
  const float* lab  = (const float*)d_in[1];
  const float* img  = (const float*)d_in[2];
  const float* W    = (const float*)d_in[3];
  const float* asrc = (const float*)d_in[4];
  const float* adst = (const float*)d_in[5];
  const float* bias = (const float*)d_in[6];
  const float* lng  = (const float*)d_in[7];
  const float* lnb  = (const float*)d_in[8];
  float* out = (float*)d_out;

  k_pack<<<(MROWS*HH+255)/256, 256>>>(text, lab, img);
  k_cvtW<<<dim3(24,24,3), dim3(32,32)>>>(W);
  k_norm<<<BB*8, 128>>>(lab, img);
  k_topk<<<BB*TT, 128>>>(text, lab, img);

  for (int l=0; l<NLAY; l++){
    k_cvtH<<<(MROWS*HH+255)/256, 256>>>();
    k_gemm_mma<<<dim3(6,65), 256>>>(l);
    k_scal<<<MROWS, 128>>>(asrc + l*NHEAD*DH, adst + l*NHEAD*DH);
    k_ms<<<BB*8, 256>>>();
    k_alpha<<<(BB*TT*8+255)/256, 256>>>();
    k_text<<<BB*TT, 256>>>(bias + l*HH, lng + l*HH, lnb + l*HH);
    k_agg<<<BB*8*SPLIT, 256>>>();
    k_big<<<BB*8, 256>>>(bias + l*HH, lng + l*HH, lnb + l*HH);
  }
  k_out<<<(BB*TT*HH+255)/256, 256>>>(out);
}

// round 5
// speedup vs baseline: 1.7011x; 1.1758x over previous
#include <cuda_runtime.h>
#include <cuda_bf16.h>
#include <math.h>
#include <cstdint>

#define BB 8
#define TT 1024
#define LLn 4
#define IIn 4
#define HH 768
#define NHEAD 4
#define DH 192
#define NLAY 3
#define NN (TT+LLn+IIn)      /* 1032 */
#define MROWS (BB*NN)        /* 8256 */

__device__ float g_h [MROWS*HH];
__device__ float g_hw[MROWS*HH];
__device__ float g_es[MROWS*NHEAD];
__device__ float g_ed[MROWS*NHEAD];
__device__ int   g_minL[BB*TT];
__device__ int   g_minI[BB*TT];
__device__ float g_nrm[BB*8];
__device__ float g_m[BB*8*NHEAD];
__device__ float g_s[BB*8*NHEAD];
__device__ float g_agg[BB*8*HH];

// bf16 split operands for tensor-core GEMM
__device__ __nv_bfloat16 g_hh[MROWS*HH];
__device__ __nv_bfloat16 g_hl[MROWS*HH];
__device__ __nv_bfloat16 g_wh[NLAY*HH*HH];   // transposed: [n][k]
__device__ __nv_bfloat16 g_wl[NLAY*HH*HH];

__device__ __forceinline__ float lrelu(float x){ return x>0.f ? x : 0.2f*x; }

// ---------------- pack inputs into node state (+bf16 split) ----------------
__global__ void k_pack(const float* __restrict__ text,const float* __restrict__ lab,
                       const float* __restrict__ img){
  int idx = blockIdx.x*256 + threadIdx.x;
  if (idx >= MROWS*HH) return;
  int c = idx % HH;
  int n = (idx / HH) % NN;
  int b = idx / (NN*HH);
  float v;
  if (n < TT)            v = text[((size_t)b*TT + n)*HH + c];
  else if (n < TT+LLn)   v = lab [((size_t)b*LLn + (n-TT))*HH + c];
  else                   v = img [((size_t)b*IIn + (n-TT-LLn))*HH + c];
  g_h[idx] = v;
  __nv_bfloat16 hi = __float2bfloat16(v);
  g_hh[idx] = hi;
  g_hl[idx] = __float2bfloat16(v - __bfloat162float(hi));
}

// ---------------- convert weights: transpose + bf16 split (all layers) ----------------
__global__ void k_cvtW(const float* __restrict__ W){
  __shared__ float tile[32][33];
  int l = blockIdx.z;
  int n0 = blockIdx.x*32, k0 = blockIdx.y*32;
  const float* Wl = W + (size_t)l*HH*HH;
  tile[threadIdx.y][threadIdx.x] = Wl[(size_t)(k0+threadIdx.y)*HH + n0+threadIdx.x];
  __syncthreads();
  float x = tile[threadIdx.x][threadIdx.y];      // = Wl[k0+tx][n0+ty]
  __nv_bfloat16 hi = __float2bfloat16(x);
  __nv_bfloat16 lo = __float2bfloat16(x - __bfloat162float(hi));
  size_t o = (size_t)l*HH*HH + (size_t)(n0+threadIdx.y)*HH + (k0+threadIdx.x);
  g_wh[o] = hi; g_wl[o] = lo;
}

// ---------------- zero es/ed before GEMM's fused atomic reduction ----------------
__global__ void k_zero(){
  int i = blockIdx.x*256 + threadIdx.x;
  if (i < MROWS*NHEAD){ g_es[i]=0.f; g_ed[i]=0.f; }
}

// ---------------- per-sample label/image norms ----------------
__global__ void k_norm(const float* __restrict__ lab,const float* __restrict__ img){
  int b = blockIdx.x / 8, j = blockIdx.x % 8;
  const float* row = (j<LLn) ? (lab + ((size_t)b*LLn + j)*HH)
                             : (img + ((size_t)b*IIn + (j-LLn))*HH);
  float s = 0.f;
  for (int c=threadIdx.x; c<HH; c+=128){ float v=row[c]; s += v*v; }
  __shared__ float red[128];
  red[threadIdx.x]=s; __syncthreads();
  for (int st=64; st>0; st>>=1){
    if (threadIdx.x<st) red[threadIdx.x]+=red[threadIdx.x+st];
    __syncthreads();
  }
  if (threadIdx.x==0) g_nrm[blockIdx.x] = sqrtf(red[0]);
}

// ---------------- top-k (store excluded argmin), float4 loads ----------------
__global__ void k_topk(const float* __restrict__ text,const float* __restrict__ lab,
                       const float* __restrict__ img){
  int bt = blockIdx.x;
  int b = bt / TT, t = bt % TT;
  const float4* trow = (const float4*)(text + ((size_t)b*TT + t)*HH);
  const float4* lb = (const float4*)(lab + (size_t)b*LLn*HH);
  const float4* im = (const float4*)(img + (size_t)b*IIn*HH);
  float acc[9];
  #pragma unroll
  for (int i=0;i<9;i++) acc[i]=0.f;
  for (int c=threadIdx.x; c<HH/4; c+=128){
    float4 tv = trow[c];
    acc[0] += tv.x*tv.x + tv.y*tv.y + tv.z*tv.z + tv.w*tv.w;
    #pragma unroll
    for (int j=0;j<4;j++){
      float4 lv = lb[j*(HH/4)+c];
      acc[1+j] += tv.x*lv.x + tv.y*lv.y + tv.z*lv.z + tv.w*lv.w;
    }
    #pragma unroll
    for (int j=0;j<4;j++){
      float4 iv = im[j*(HH/4)+c];
      acc[5+j] += tv.x*iv.x + tv.y*iv.y + tv.z*iv.z + tv.w*iv.w;
    }
  }
  __shared__ float red[9][4];
  int lane=threadIdx.x&31, w=threadIdx.x>>5;
  #pragma unroll
  for (int i=0;i<9;i++){
    float v=acc[i];
    for (int o=16;o>0;o>>=1) v += __shfl_down_sync(0xffffffffu,v,o);
    if (lane==0) red[i][w]=v;
  }
  __syncthreads();
  if (threadIdx.x==0){
    float tot[9];
    #pragma unroll
    for (int i=0;i<9;i++) tot[i]=red[i][0]+red[i][1]+red[i][2]+red[i][3];
    float tn = sqrtf(tot[0]);
    int amL=0; float mvL=3.4e38f;
    for (int j=0;j<4;j++){
      float den = fmaxf(tn*g_nrm[b*8+j], 1e-8f);
      float s = tot[1+j]/den;
      if (s<mvL){ mvL=s; amL=j; }
    }
    g_minL[bt]=amL;
    int amI=0; float mvI=3.4e38f;
    for (int j=0;j<4;j++){
      float den = fmaxf(tn*g_nrm[b*8+4+j], 1e-8f);
      float s = tot[5+j]/den;
      if (s<mvI){ mvI=s; amI=j; }
    }
    g_minI[bt]=amI;
  }
}

// ======================= HMMA GEMM (mma.sync bf16, 3-term split) =======================
// g_hw = g_h @ W[l].  CTA tile 128x128, k-step 32, double-buffered cp.async.
// Fused epilogue: es/ed partial dot products via quad-reduce + atomicAdd.
#define APAD 40
#define STAGE_B (128*APAD)

__device__ __forceinline__ uint32_t smem_u32(const void* p){
  return (uint32_t)__cvta_generic_to_shared(p);
}
__device__ __forceinline__ void cp16(uint32_t dst, const void* src){
  asm volatile("cp.async.cg.shared.global [%0], [%1], 16;" :: "r"(dst), "l"(src));
}
__device__ __forceinline__ void cp_commit(){ asm volatile("cp.async.commit_group;"); }
__device__ __forceinline__ void cp_wait1(){ asm volatile("cp.async.wait_group 1;"); }
__device__ __forceinline__ void cp_wait0(){ asm volatile("cp.async.wait_group 0;"); }
__device__ __forceinline__ void ldmx4(uint32_t a, uint32_t& r0, uint32_t& r1, uint32_t& r2, uint32_t& r3){
  asm volatile("ldmatrix.sync.aligned.m8n8.x4.shared.b16 {%0,%1,%2,%3}, [%4];"
    : "=r"(r0), "=r"(r1), "=r"(r2), "=r"(r3) : "r"(a));
}
__device__ __forceinline__ void mma16816(float* d, const uint32_t* a, uint32_t b0, uint32_t b1){
  asm volatile(
    "mma.sync.aligned.m16n8k16.row.col.f32.bf16.bf16.f32 "
    "{%0,%1,%2,%3}, {%4,%5,%6,%7}, {%8,%9}, {%0,%1,%2,%3};"
    : "+f"(d[0]), "+f"(d[1]), "+f"(d[2]), "+f"(d[3])
    : "r"(a[0]), "r"(a[1]), "r"(a[2]), "r"(a[3]), "r"(b0), "r"(b1));
}

__global__ void __launch_bounds__(256,2) k_gemm_mma(int layer,
    const float* __restrict__ asrc, const float* __restrict__ adst){
  __shared__ __nv_bfloat16 As[2][STAGE_B];
  __shared__ __nv_bfloat16 Bs[2][STAGE_B];

  int tid = threadIdx.x;
  int wid = tid >> 5, lane = tid & 31;
  int wm = wid & 3, wn = wid >> 2;
  int bx = blockIdx.x;
  int by = blockIdx.y;

  const __nv_bfloat16* wH = g_wh + (size_t)layer*HH*HH;
  const __nv_bfloat16* wL = g_wl + (size_t)layer*HH*HH;

  int lr0 = tid >> 2,        lc0 = (tid & 3) * 8;
  int lr1 = (tid+256) >> 2,  lc1 = lc0;
  int am0 = by*128 + lr0; if (am0 >= MROWS) am0 = MROWS-1;
  int am1 = by*128 + lr1; if (am1 >= MROWS) am1 = MROWS-1;
  int bn0 = bx*128 + lr0;
  int bn1 = bx*128 + lr1;
  uint32_t sA = smem_u32(&As[0][0]);
  uint32_t sB = smem_u32(&Bs[0][0]);
  uint32_t dA0 = sA + (uint32_t)(lr0*APAD + lc0)*2;
  uint32_t dA1 = sA + (uint32_t)(lr1*APAD + lc1)*2;
  uint32_t dB0 = sB + (uint32_t)(lr0*APAD + lc0)*2;
  uint32_t dB1 = sB + (uint32_t)(lr1*APAD + lc1)*2;

  uint32_t aRow = (uint32_t)(wm*32 + ((lane>>3)&1)*8 + (lane&7));
  uint32_t aCol = (uint32_t)(((lane>>4)&1)*8);
  uint32_t bRow = (uint32_t)(wn*64 + ((lane>>4)&1)*8 + (lane&7));
  uint32_t bCol = (uint32_t)(((lane>>3)&1)*8);

  float acc[2][8][4];
  #pragma unroll
  for (int i=0;i<2;i++)
    #pragma unroll
    for (int j=0;j<8;j++)
      #pragma unroll
      for (int k=0;k<4;k++) acc[i][j][k]=0.f;

  const int NSTAGE = 72;
  auto issue = [&](int s){
    int term = s / 24;
    int k0 = (s % 24) * 32;
    int buf = s & 1;
    const __nv_bfloat16* aS = (term < 2) ? g_hh : g_hl;
    const __nv_bfloat16* bS = (term == 1) ? wL : wH;
    uint32_t off = (uint32_t)(buf * STAGE_B) * 2;
    cp16(dA0 + off, aS + (size_t)am0*HH + k0 + lc0);
    cp16(dA1 + off, aS + (size_t)am1*HH + k0 + lc1);
    cp16(dB0 + off, bS + (size_t)bn0*HH + k0 + lc0);
    cp16(dB1 + off, bS + (size_t)bn1*HH + k0 + lc1);
    cp_commit();
  };

  issue(0);
  for (int s = 0; s < NSTAGE; s++){
    if (s+1 < NSTAGE){ issue(s+1); cp_wait1(); }
    else cp_wait0();
    __syncthreads();
    int buf = s & 1;
    uint32_t aBase = sA + (uint32_t)(buf*STAGE_B)*2;
    uint32_t bBase = sB + (uint32_t)(buf*STAGE_B)*2;
    #pragma unroll
    for (int kk = 0; kk < 32; kk += 16){
      uint32_t a[2][4], b[4][4];
      #pragma unroll
      for (int mt=0; mt<2; mt++){
        uint32_t ad = aBase + ((aRow + mt*16)*APAD + aCol + kk)*2;
        ldmx4(ad, a[mt][0], a[mt][1], a[mt][2], a[mt][3]);
      }
      #pragma unroll
      for (int nt=0; nt<4; nt++){
        uint32_t bd = bBase + ((bRow + nt*16)*APAD + bCol + kk)*2;
        ldmx4(bd, b[nt][0], b[nt][1], b[nt][2], b[nt][3]);
      }
      #pragma unroll
      for (int mt=0; mt<2; mt++)
        #pragma unroll
        for (int n=0; n<8; n++){
          int nt = n >> 1, pr = n & 1;
          mma16816(acc[mt][n], a[mt], b[nt][pr*2], b[nt][pr*2+1]);
        }
    }
    __syncthreads();
  }

  // epilogue 1: write accumulators to g_hw
  #pragma unroll
  for (int mt=0; mt<2; mt++){
    int r0 = by*128 + wm*32 + mt*16 + (lane>>2);
    #pragma unroll
    for (int n=0; n<8; n++){
      int c0 = bx*128 + wn*64 + n*8 + (lane&3)*2;
      if (r0 < MROWS)
        *(float2*)(g_hw + (size_t)r0*HH + c0) = make_float2(acc[mt][n][0], acc[mt][n][1]);
      if (r0+8 < MROWS)
        *(float2*)(g_hw + (size_t)(r0+8)*HH + c0) = make_float2(acc[mt][n][2], acc[mt][n][3]);
    }
  }

  // epilogue 2: fused es/ed reduction. This warp's 64 cols lie in one head.
  int head = (bx*128 + wn*64) / DH;
  #pragma unroll
  for (int mt=0; mt<2; mt++){
    float ses0=0.f, sed0=0.f, ses1=0.f, sed1=0.f;
    #pragma unroll
    for (int n=0; n<8; n++){
      int c = bx*128 + wn*64 + n*8 + (lane&3)*2;
      float a0=asrc[c], a1=asrc[c+1], d0=adst[c], d1=adst[c+1];
      ses0 += acc[mt][n][0]*a0 + acc[mt][n][1]*a1;
      sed0 += acc[mt][n][0]*d0 + acc[mt][n][1]*d1;
      ses1 += acc[mt][n][2]*a0 + acc[mt][n][3]*a1;
      sed1 += acc[mt][n][2]*d0 + acc[mt][n][3]*d1;
    }
    #pragma unroll
    for (int o=1; o<=2; o<<=1){
      ses0 += __shfl_xor_sync(0xffffffffu, ses0, o);
      sed0 += __shfl_xor_sync(0xffffffffu, sed0, o);
      ses1 += __shfl_xor_sync(0xffffffffu, ses1, o);
      sed1 += __shfl_xor_sync(0xffffffffu, sed1, o);
    }
    if ((lane&3)==0){
      int r0 = by*128 + wm*32 + mt*16 + (lane>>2);
      if (r0 < MROWS){
        atomicAdd(&g_es[r0*NHEAD+head], ses0);
        atomicAdd(&g_ed[r0*NHEAD+head], sed0);
      }
      if (r0+8 < MROWS){
        atomicAdd(&g_es[(r0+8)*NHEAD+head], ses1);
        atomicAdd(&g_ed[(r0+8)*NHEAD+head], sed1);
      }
    }
  }
}

// 8 static in-edges for big node j (0..3 = label j, 4..7 = image j-4)
__device__ __forceinline__ int static_src(int j,int s){
  if (j<LLn){
    if (s<4) return TT+LLn+s;
    if (s<7){ int p=s-4; if(p>=j)p++; return TT+p; }
    return TT+j;
  } else {
    int jj=j-LLn;
    if (s<4) return TT+s;
    if (s<7){ int p=s-4; if(p>=jj)p++; return TT+LLn+p; }
    return TT+LLn+jj;
  }
}

// ---------------- big-node softmax max & sumexp (and zero agg) ----------------
__global__ void k_ms(){
  int b = blockIdx.x>>3, j = blockIdx.x&7;
  int tid = threadIdx.x;
  int jj = (j<LLn)? j : j-LLn;
  int dst = (j<LLn)? (TT+j) : (TT+LLn+jj);
  for (int c=tid;c<HH;c+=256) g_agg[blockIdx.x*HH+c]=0.f;
  float edv[4];
  #pragma unroll
  for (int h=0;h<4;h++) edv[h]=g_ed[(size_t)(b*NN+dst)*NHEAD+h];
  const int* minA = (j<LLn)? (g_minL+b*TT) : (g_minI+b*TT);
  float mx[4]={-3.4e38f,-3.4e38f,-3.4e38f,-3.4e38f};
  for (int t=tid;t<TT;t+=256){
    if (minA[t]!=jj){
      const float* e = g_es + (size_t)(b*NN+t)*NHEAD;
      #pragma unroll
      for (int h=0;h<4;h++) mx[h]=fmaxf(mx[h], lrelu(e[h]+edv[h]));
    }
  }
  if (tid==0){
    #pragma unroll
    for (int s=0;s<8;s++){
      int sr = static_src(j,s);
      const float* e = g_es + (size_t)(b*NN+sr)*NHEAD;
      #pragma unroll
      for (int h=0;h<4;h++) mx[h]=fmaxf(mx[h], lrelu(e[h]+edv[h]));
    }
  }
  __shared__ float red[256][4];
  #pragma unroll
  for (int h=0;h<4;h++) red[tid][h]=mx[h];
  __syncthreads();
  for (int st=128;st>0;st>>=1){
    if (tid<st){
      #pragma unroll
      for (int h=0;h<4;h++) red[tid][h]=fmaxf(red[tid][h],red[tid+st][h]);
    }
    __syncthreads();
  }
  float mv[4];
  #pragma unroll
  for (int h=0;h<4;h++) mv[h]=red[0][h];
  __syncthreads();
  float sm[4]={0.f,0.f,0.f,0.f};
  for (int t=tid;t<TT;t+=256){
    if (minA[t]!=jj){
      const float* e = g_es + (size_t)(b*NN+t)*NHEAD;
      #pragma unroll
      for (int h=0;h<4;h++) sm[h] += __expf(lrelu(e[h]+edv[h])-mv[h]);
    }
  }
  if (tid==0){
    #pragma unroll
    for (int s=0;s<8;s++){
      int sr = static_src(j,s);
      const float* e = g_es + (size_t)(b*NN+sr)*NHEAD;
      #pragma unroll
      for (int h=0;h<4;h++) sm[h] += __expf(lrelu(e[h]+edv[h])-mv[h]);
    }
  }
  #pragma unroll
  for (int h=0;h<4;h++) red[tid][h]=sm[h];
  __syncthreads();
  for (int st=128;st>0;st>>=1){
    if (tid<st){
      #pragma unroll
      for (int h=0;h<4;h++) red[tid][h]+=red[tid+st][h];
    }
    __syncthreads();
  }
  if (tid<4){
    g_m[(b*8+j)*NHEAD+tid]=mv[tid];
    g_s[(b*8+j)*NHEAD+tid]=red[0][tid];
  }
}

// ---------------- big-node weighted aggregation (all 8 j per block, alpha inline) ----------------
__global__ void k_agg(){
  int b  = blockIdx.x >> 5;
  int sp = blockIdx.x & 31;
  int tid = threadIdx.x;
  int t0 = sp*32;
  __shared__ float sal[32][8][4];
  #pragma unroll
  for (int q=0;q<4;q++){
    int idx = tid + q*256;          // 0..1023
    int tl = idx >> 5;
    int j  = (idx >> 2) & 7;
    int h  = idx & 3;
    int jj = (j<LLn)? j : j-LLn;
    int dst = (j<LLn)? (TT+j) : (TT+LLn+jj);
    int t = t0 + tl;
    int excl = (j<LLn)? (g_minL[b*TT+t]==jj) : (g_minI[b*TT+t]==jj);
    float al = 0.f;
    if (!excl){
      float e = lrelu(g_es[(size_t)(b*NN+t)*NHEAD+h] + g_ed[(size_t)(b*NN+dst)*NHEAD+h]);
      al = __expf(e - g_m[(b*8+j)*NHEAD+h]) / g_s[(b*8+j)*NHEAD+h];
    }
    sal[tl][j][h] = al;
  }
  __syncthreads();
  int c0=tid, c1=tid+256, c2=tid+512;
  int h0=c0/DH, h1=c1/DH, h2=c2/DH;
  float a0[8], a1[8], a2[8];
  #pragma unroll
  for (int j=0;j<8;j++){ a0[j]=0.f; a1[j]=0.f; a2[j]=0.f; }
  for (int tl=0; tl<32; tl++){
    const float* hr = g_hw + (size_t)(b*NN + t0+tl)*HH;
    float v0=hr[c0], v1=hr[c1], v2=hr[c2];
    #pragma unroll
    for (int j=0;j<8;j++){
      a0[j] += sal[tl][j][h0]*v0;
      a1[j] += sal[tl][j][h1]*v1;
      a2[j] += sal[tl][j][h2]*v2;
    }
  }
  #pragma unroll
  for (int j=0;j<8;j++){
    atomicAdd(&g_agg[(b*8+j)*HH+c0], a0[j]);
    atomicAdd(&g_agg[(b*8+j)*HH+c1], a1[j]);
    atomicAdd(&g_agg[(b*8+j)*HH+c2], a2[j]);
  }
}

// ---------------- big-node epilogue: static edges + bias+relu+residual+LN (+conv) ----------------
__global__ void k_big(const float* __restrict__ bias,const float* __restrict__ lng,
                      const float* __restrict__ lnb){
  int b = blockIdx.x>>3, j = blockIdx.x&7;
  int jj = (j<LLn)? j : j-LLn;
  int node = (j<LLn)? (TT+j) : (TT+LLn+jj);
  int tid = threadIdx.x;
  __shared__ float sal[8][4];
  __shared__ int ssrc[8];
  if (tid<32){
    int s=tid>>2, h=tid&3;
    int sr = static_src(j,s);
    if (h==0) ssrc[s]=sr;
    float e = lrelu(g_es[(size_t)(b*NN+sr)*NHEAD+h] + g_ed[(size_t)(b*NN+node)*NHEAD+h]);
    sal[s][h] = __expf(e - g_m[(b*8+j)*NHEAD+h]) / g_s[(b*8+j)*NHEAD+h];
  }
  __syncthreads();
  size_t row = (size_t)(b*NN+node)*HH;
  float v[3]; float s=0.f, sq=0.f;
  #pragma unroll
  for (int r=0;r<3;r++){
    int c = tid + 256*r;
    int hd = c/DH;
    float o = g_agg[(b*8+j)*HH+c];
    #pragma unroll
    for (int e=0;e<8;e++)
      o += sal[e][hd] * g_hw[(size_t)(b*NN+ssrc[e])*HH + c];
    o = fmaxf(o + bias[c], 0.f);
    float y = o + g_h[row+c];
    v[r]=y; s+=y; sq+=y*y;
  }
  __shared__ float rs[256], rq[256];
  rs[tid]=s; rq[tid]=sq; __syncthreads();
  for (int st=128;st>0;st>>=1){
    if (tid<st){ rs[tid]+=rs[tid+st]; rq[tid]+=rq[tid+st]; }
    __syncthreads();
  }
  float mu = rs[0]*(1.f/HH);
  float var = rq[0]*(1.f/HH) - mu*mu;
  float rstd = rsqrtf(var + 1e-5f);
  #pragma unroll
  for (int r=0;r<3;r++){
    int c = tid + 256*r;
    float y = (v[r]-mu)*rstd*lng[c] + lnb[c];
    g_h[row+c] = y;
    __nv_bfloat16 hi = __float2bfloat16(y);
    g_hh[row+c] = hi;
    g_hl[row+c] = __float2bfloat16(y - __bfloat162float(hi));
  }
}

// ---------------- text-node: full fused attention + epilogue (+conv or ->out) ----------------
__global__ void k_text(const float* __restrict__ bias,const float* __restrict__ lng,
                       const float* __restrict__ lnb, float* __restrict__ outp, int last){
  int bt = blockIdx.x;
  int b = bt/TT, t = bt%TT;
  int tid = threadIdx.x;
  __shared__ int ssrc[9];
  __shared__ int snum;
  __shared__ float sal[9][4];
  if (tid==0){
    int n=0;
    ssrc[n++]=t;
    if (t>0)    ssrc[n++]=t-1;
    if (t<TT-1) ssrc[n++]=t+1;
    int ml=g_minL[bt], mi=g_minI[bt];
    #pragma unroll
    for (int j2=0;j2<4;j2++) if (j2!=ml) ssrc[n++]=TT+j2;
    #pragma unroll
    for (int j2=0;j2<4;j2++) if (j2!=mi) ssrc[n++]=TT+LLn+j2;
    snum=n;
  }
  __syncthreads();
  int ns = snum;
  if (tid<4){
    float ed = g_ed[(size_t)(b*NN+t)*NHEAD + tid];
    float ev[9]; float mxv=-3.4e38f;
    for (int e=0;e<ns;e++){
      float x = lrelu(g_es[(size_t)(b*NN+ssrc[e])*NHEAD + tid] + ed);
      ev[e]=x; mxv=fmaxf(mxv,x);
    }
    float sm=0.f;
    for (int e=0;e<ns;e++){ float w=__expf(ev[e]-mxv); ev[e]=w; sm+=w; }
    float inv = 1.f/sm;
    for (int e=0;e<ns;e++) sal[e][tid]=ev[e]*inv;
  }
  __syncthreads();
  size_t row = (size_t)(b*NN+t)*HH;
  float v[3]; float s=0.f, sq=0.f;
  #pragma unroll
  for (int r=0;r<3;r++){
    int c = tid + 256*r;
    int hd = c/DH;
    float a = 0.f;
    for (int e=0;e<ns;e++)
      a += sal[e][hd] * g_hw[(size_t)(b*NN+ssrc[e])*HH + c];
    float o = fmaxf(a + bias[c], 0.f);
    float y = o + g_h[row+c];
    v[r]=y; s+=y; sq+=y*y;
  }
  __shared__ float rs[256], rq[256];
  rs[tid]=s; rq[tid]=sq; __syncthreads();
  for (int st=128;st>0;st>>=1){
    if (tid<st){ rs[tid]+=rs[tid+st]; rq[tid]+=rq[tid+st]; }
    __syncthreads();
  }
  float mu = rs[0]*(1.f/HH);
  float var = rq[0]*(1.f/HH) - mu*mu;
  float rstd = rsqrtf(var + 1e-5f);
  if (last){
    float* od = outp + ((size_t)b*TT + t)*HH;
    #pragma unroll
    for (int r=0;r<3;r++){
      int c = tid + 256*r;
      od[c] = (v[r]-mu)*rstd*lng[c] + lnb[c];
    }
  } else {
    #pragma unroll
    for (int r=0;r<3;r++){
      int c = tid + 256*r;
      float y = (v[r]-mu)*rstd*lng[c] + lnb[c];
      g_h[row+c] = y;
      __nv_bfloat16 hi = __float2bfloat16(y);
      g_hh[row+c] = hi;
      g_hl[row+c] = __float2bfloat16(y - __bfloat162float(hi));
    }
  }
}

extern "C" void kernel_launch(void* const* d_in, const int* in_sizes, int n_in,
                              void* d_out, int out_size) {
  const float* text = (const float*)d_in[0];
  const float* lab  = (const float*)d_in[1];
  const float* img  = (const float*)d_in[2];
  const float* W    = (const float*)d_in[3];
  const float* asrc = (const float*)d_in[4];
  const float* adst = (const float*)d_in[5];
  const float* bias = (const float*)d_in[6];
  const float* lng  = (const float*)d_in[7];
  const float* lnb  = (const float*)d_in[8];
  float* out = (float*)d_out;

  k_pack<<<(MROWS*HH+255)/256, 256>>>(text, lab, img);
  k_cvtW<<<dim3(24,24,3), dim3(32,32)>>>(W);
  k_norm<<<BB*8, 128>>>(lab, img);
  k_topk<<<BB*TT, 128>>>(text, lab, img);

  for (int l=0; l<NLAY; l++){
    int last = (l == NLAY-1);
    k_zero<<<(MROWS*NHEAD+255)/256, 256>>>();
    k_gemm_mma<<<dim3(6,65), 256>>>(l, asrc + l*NHEAD*DH, adst + l*NHEAD*DH);
    if (!last){
      k_ms<<<BB*8, 256>>>();
      k_agg<<<BB*32, 256>>>();
      k_big<<<BB*8, 256>>>(bias + l*HH, lng + l*HH, lnb + l*HH);
    }
    k_text<<<BB*TT, 256>>>(bias + l*HH, lng + l*HH, lnb + l*HH, out, last);
  }
}

// round 6
// speedup vs baseline: 1.9811x; 1.1646x over previous
#include <cuda_runtime.h>
#include <cuda_bf16.h>
#include <math.h>
#include <cstdint>

#define BB 8
#define TT 1024
#define LLn 4
#define IIn 4
#define HH 768
#define NHEAD 4
#define DH 192
#define NLAY 3
#define NN (TT+LLn+IIn)      /* 1032 */
#define MROWS (BB*NN)        /* 8256 */

__device__ float g_h [MROWS*HH];
__device__ float g_hw[MROWS*HH];
__device__ float g_es[MROWS*NHEAD];
__device__ float g_ed[MROWS*NHEAD];
__device__ int   g_minL[BB*TT];
__device__ int   g_minI[BB*TT];
__device__ float g_nrm[BB*8];
__device__ float g_m[BB*8*NHEAD];
__device__ float g_s[BB*8*NHEAD];
__device__ float g_agg[BB*8*HH];

// bf16 split operands for tensor-core GEMM
__device__ __nv_bfloat16 g_hh[MROWS*HH];
__device__ __nv_bfloat16 g_hl[MROWS*HH];
__device__ __nv_bfloat16 g_wh[NLAY*HH*HH];   // transposed: [n][k]
__device__ __nv_bfloat16 g_wl[NLAY*HH*HH];

__device__ __forceinline__ float lrelu(float x){ return x>0.f ? x : 0.2f*x; }

// ---------------- pack inputs into node state (+bf16 split) ----------------
__global__ void k_pack(const float* __restrict__ text,const float* __restrict__ lab,
                       const float* __restrict__ img){
  int idx = blockIdx.x*256 + threadIdx.x;
  if (idx >= MROWS*HH) return;
  int c = idx % HH;
  int n = (idx / HH) % NN;
  int b = idx / (NN*HH);
  float v;
  if (n < TT)            v = text[((size_t)b*TT + n)*HH + c];
  else if (n < TT+LLn)   v = lab [((size_t)b*LLn + (n-TT))*HH + c];
  else                   v = img [((size_t)b*IIn + (n-TT-LLn))*HH + c];
  g_h[idx] = v;
  __nv_bfloat16 hi = __float2bfloat16(v);
  g_hh[idx] = hi;
  g_hl[idx] = __float2bfloat16(v - __bfloat162float(hi));
}

// ---------------- convert weights: transpose + bf16 split (all layers) ----------------
__global__ void k_cvtW(const float* __restrict__ W){
  __shared__ float tile[32][33];
  int l = blockIdx.z;
  int n0 = blockIdx.x*32, k0 = blockIdx.y*32;
  const float* Wl = W + (size_t)l*HH*HH;
  tile[threadIdx.y][threadIdx.x] = Wl[(size_t)(k0+threadIdx.y)*HH + n0+threadIdx.x];
  __syncthreads();
  float x = tile[threadIdx.x][threadIdx.y];      // = Wl[k0+tx][n0+ty]
  __nv_bfloat16 hi = __float2bfloat16(x);
  __nv_bfloat16 lo = __float2bfloat16(x - __bfloat162float(hi));
  size_t o = (size_t)l*HH*HH + (size_t)(n0+threadIdx.y)*HH + (k0+threadIdx.x);
  g_wh[o] = hi; g_wl[o] = lo;
}

// ---------------- zero es/ed before GEMM's fused atomic reduction ----------------
__global__ void k_zero(){
  int i = blockIdx.x*256 + threadIdx.x;
  if (i < MROWS*NHEAD){ g_es[i]=0.f; g_ed[i]=0.f; }
}

// ---------------- per-sample label/image norms ----------------
__global__ void k_norm(const float* __restrict__ lab,const float* __restrict__ img){
  int b = blockIdx.x / 8, j = blockIdx.x % 8;
  const float* row = (j<LLn) ? (lab + ((size_t)b*LLn + j)*HH)
                             : (img + ((size_t)b*IIn + (j-LLn))*HH);
  float s = 0.f;
  for (int c=threadIdx.x; c<HH; c+=128){ float v=row[c]; s += v*v; }
  __shared__ float red[128];
  red[threadIdx.x]=s; __syncthreads();
  for (int st=64; st>0; st>>=1){
    if (threadIdx.x<st) red[threadIdx.x]+=red[threadIdx.x+st];
    __syncthreads();
  }
  if (threadIdx.x==0) g_nrm[blockIdx.x] = sqrtf(red[0]);
}

// ---------------- top-k (store excluded argmin), float4 loads ----------------
__global__ void k_topk(const float* __restrict__ text,const float* __restrict__ lab,
                       const float* __restrict__ img){
  int bt = blockIdx.x;
  int b = bt / TT, t = bt % TT;
  const float4* trow = (const float4*)(text + ((size_t)b*TT + t)*HH);
  const float4* lb = (const float4*)(lab + (size_t)b*LLn*HH);
  const float4* im = (const float4*)(img + (size_t)b*IIn*HH);
  float acc[9];
  #pragma unroll
  for (int i=0;i<9;i++) acc[i]=0.f;
  for (int c=threadIdx.x; c<HH/4; c+=128){
    float4 tv = trow[c];
    acc[0] += tv.x*tv.x + tv.y*tv.y + tv.z*tv.z + tv.w*tv.w;
    #pragma unroll
    for (int j=0;j<4;j++){
      float4 lv = lb[j*(HH/4)+c];
      acc[1+j] += tv.x*lv.x + tv.y*lv.y + tv.z*lv.z + tv.w*lv.w;
    }
    #pragma unroll
    for (int j=0;j<4;j++){
      float4 iv = im[j*(HH/4)+c];
      acc[5+j] += tv.x*iv.x + tv.y*iv.y + tv.z*iv.z + tv.w*iv.w;
    }
  }
  __shared__ float red[9][4];
  int lane=threadIdx.x&31, w=threadIdx.x>>5;
  #pragma unroll
  for (int i=0;i<9;i++){
    float v=acc[i];
    for (int o=16;o>0;o>>=1) v += __shfl_down_sync(0xffffffffu,v,o);
    if (lane==0) red[i][w]=v;
  }
  __syncthreads();
  if (threadIdx.x==0){
    float tot[9];
    #pragma unroll
    for (int i=0;i<9;i++) tot[i]=red[i][0]+red[i][1]+red[i][2]+red[i][3];
    float tn = sqrtf(tot[0]);
    int amL=0; float mvL=3.4e38f;
    for (int j=0;j<4;j++){
      float den = fmaxf(tn*g_nrm[b*8+j], 1e-8f);
      float s = tot[1+j]/den;
      if (s<mvL){ mvL=s; amL=j; }
    }
    g_minL[bt]=amL;
    int amI=0; float mvI=3.4e38f;
    for (int j=0;j<4;j++){
      float den = fmaxf(tn*g_nrm[b*8+4+j], 1e-8f);
      float s = tot[5+j]/den;
      if (s<mvI){ mvI=s; amI=j; }
    }
    g_minI[bt]=amI;
  }
}

// ======================= HMMA GEMM (mma.sync bf16, 3-term split) =======================
// g_hw = g_h @ W[l].  CTA tile 128x128, k-step 32, 24 stages (all 4 operand tiles
// loaded per stage; 3 MMA term-combos issued against them). Double-buffered cp.async.
#define APAD 40
#define TILE_E (128*APAD)          /* 5120 elements per tile */
#define BUF_E  (4*TILE_E)          /* 20480 elements per stage buffer */
#define GEMM_SMEM (2*BUF_E*2)      /* bytes: 81920 */

__device__ __forceinline__ uint32_t smem_u32(const void* p){
  return (uint32_t)__cvta_generic_to_shared(p);
}
__device__ __forceinline__ void cp16(uint32_t dst, const void* src){
  asm volatile("cp.async.cg.shared.global [%0], [%1], 16;" :: "r"(dst), "l"(src));
}
__device__ __forceinline__ void cp_commit(){ asm volatile("cp.async.commit_group;"); }
__device__ __forceinline__ void cp_wait1(){ asm volatile("cp.async.wait_group 1;"); }
__device__ __forceinline__ void cp_wait0(){ asm volatile("cp.async.wait_group 0;"); }
__device__ __forceinline__ void ldmx4(uint32_t a, uint32_t& r0, uint32_t& r1, uint32_t& r2, uint32_t& r3){
  asm volatile("ldmatrix.sync.aligned.m8n8.x4.shared.b16 {%0,%1,%2,%3}, [%4];"
    : "=r"(r0), "=r"(r1), "=r"(r2), "=r"(r3) : "r"(a));
}
__device__ __forceinline__ void mma16816(float* d, const uint32_t* a, uint32_t b0, uint32_t b1){
  asm volatile(
    "mma.sync.aligned.m16n8k16.row.col.f32.bf16.bf16.f32 "
    "{%0,%1,%2,%3}, {%4,%5,%6,%7}, {%8,%9}, {%0,%1,%2,%3};"
    : "+f"(d[0]), "+f"(d[1]), "+f"(d[2]), "+f"(d[3])
    : "r"(a[0]), "r"(a[1]), "r"(a[2]), "r"(a[3]), "r"(b0), "r"(b1));
}

__global__ void __launch_bounds__(256,2) k_gemm_mma(int layer,
    const float* __restrict__ asrc, const float* __restrict__ adst){
  extern __shared__ __nv_bfloat16 sm[];

  int tid = threadIdx.x;
  int wid = tid >> 5, lane = tid & 31;
  int wm = wid & 3, wn = wid >> 2;        // warp tile 32x64 inside 128x128
  int bx = blockIdx.x;
  int by = blockIdx.y;

  const __nv_bfloat16* wH = g_wh + (size_t)layer*HH*HH;
  const __nv_bfloat16* wL = g_wl + (size_t)layer*HH*HH;

  // loader mapping: each thread handles rows r0, r1 of each of the 4 tiles.
  int r0 = tid >> 2, r1 = 64 + (tid >> 2);
  int c8 = (tid & 3) * 8;
  int mA0 = by*128 + r0; if (mA0 >= MROWS) mA0 = MROWS-1;
  int mA1 = by*128 + r1; if (mA1 >= MROWS) mA1 = MROWS-1;
  int nB0 = bx*128 + r0;
  int nB1 = bx*128 + r1;
  uint32_t sBase = smem_u32(sm);
  uint32_t d0 = (uint32_t)(r0*APAD + c8)*2;
  uint32_t d1 = (uint32_t)(r1*APAD + c8)*2;

  uint32_t aRow = (uint32_t)(wm*32 + ((lane>>3)&1)*8 + (lane&7));
  uint32_t aCol = (uint32_t)(((lane>>4)&1)*8);
  uint32_t bRow = (uint32_t)(wn*64 + ((lane>>4)&1)*8 + (lane&7));
  uint32_t bCol = (uint32_t)(((lane>>3)&1)*8);

  float acc[2][8][4];
  #pragma unroll
  for (int i=0;i<2;i++)
    #pragma unroll
    for (int j=0;j<8;j++)
      #pragma unroll
      for (int k=0;k<4;k++) acc[i][j][k]=0.f;

  const int NSTAGE = 24;
  auto issue = [&](int s){
    int k0 = s * 32;
    uint32_t off = sBase + (uint32_t)((s & 1) * BUF_E) * 2;
    const __nv_bfloat16* a0 = g_hh + (size_t)mA0*HH + k0 + c8;
    const __nv_bfloat16* a1 = g_hh + (size_t)mA1*HH + k0 + c8;
    const __nv_bfloat16* l0 = g_hl + (size_t)mA0*HH + k0 + c8;
    const __nv_bfloat16* l1 = g_hl + (size_t)mA1*HH + k0 + c8;
    const __nv_bfloat16* bh0 = wH + (size_t)nB0*HH + k0 + c8;
    const __nv_bfloat16* bh1 = wH + (size_t)nB1*HH + k0 + c8;
    const __nv_bfloat16* bl0 = wL + (size_t)nB0*HH + k0 + c8;
    const __nv_bfloat16* bl1 = wL + (size_t)nB1*HH + k0 + c8;
    cp16(off + 0*TILE_E*2 + d0, a0);
    cp16(off + 0*TILE_E*2 + d1, a1);
    cp16(off + 1*TILE_E*2 + d0, l0);
    cp16(off + 1*TILE_E*2 + d1, l1);
    cp16(off + 2*TILE_E*2 + d0, bh0);
    cp16(off + 2*TILE_E*2 + d1, bh1);
    cp16(off + 3*TILE_E*2 + d0, bl0);
    cp16(off + 3*TILE_E*2 + d1, bl1);
    cp_commit();
  };

  issue(0);
  for (int s = 0; s < NSTAGE; s++){
    if (s+1 < NSTAGE){ issue(s+1); cp_wait1(); }
    else cp_wait0();
    __syncthreads();
    uint32_t buf = sBase + (uint32_t)((s & 1) * BUF_E) * 2;
    uint32_t tAh = buf, tAl = buf + TILE_E*2, tBh = buf + 2*TILE_E*2, tBl = buf + 3*TILE_E*2;
    #pragma unroll
    for (int kk = 0; kk < 32; kk += 16){
      uint32_t ah[2][4], al[2][4];
      #pragma unroll
      for (int mt=0; mt<2; mt++){
        uint32_t ro = ((aRow + mt*16)*APAD + aCol + kk)*2;
        ldmx4(tAh + ro, ah[mt][0], ah[mt][1], ah[mt][2], ah[mt][3]);
        ldmx4(tAl + ro, al[mt][0], al[mt][1], al[mt][2], al[mt][3]);
      }
      {
        uint32_t b[4][4];
        #pragma unroll
        for (int nt=0; nt<4; nt++){
          uint32_t ro = ((bRow + nt*16)*APAD + bCol + kk)*2;
          ldmx4(tBh + ro, b[nt][0], b[nt][1], b[nt][2], b[nt][3]);
        }
        #pragma unroll
        for (int mt=0; mt<2; mt++)
          #pragma unroll
          for (int n=0; n<8; n++){
            int nt = n >> 1, pr = n & 1;
            mma16816(acc[mt][n], ah[mt], b[nt][pr*2], b[nt][pr*2+1]);
            mma16816(acc[mt][n], al[mt], b[nt][pr*2], b[nt][pr*2+1]);
          }
      }
      {
        uint32_t b[4][4];
        #pragma unroll
        for (int nt=0; nt<4; nt++){
          uint32_t ro = ((bRow + nt*16)*APAD + bCol + kk)*2;
          ldmx4(tBl + ro, b[nt][0], b[nt][1], b[nt][2], b[nt][3]);
        }
        #pragma unroll
        for (int mt=0; mt<2; mt++)
          #pragma unroll
          for (int n=0; n<8; n++){
            int nt = n >> 1, pr = n & 1;
            mma16816(acc[mt][n], ah[mt], b[nt][pr*2], b[nt][pr*2+1]);
          }
      }
    }
    __syncthreads();
  }

  // epilogue 1: write accumulators to g_hw
  #pragma unroll
  for (int mt=0; mt<2; mt++){
    int rr = by*128 + wm*32 + mt*16 + (lane>>2);
    #pragma unroll
    for (int n=0; n<8; n++){
      int c0 = bx*128 + wn*64 + n*8 + (lane&3)*2;
      if (rr < MROWS)
        *(float2*)(g_hw + (size_t)rr*HH + c0) = make_float2(acc[mt][n][0], acc[mt][n][1]);
      if (rr+8 < MROWS)
        *(float2*)(g_hw + (size_t)(rr+8)*HH + c0) = make_float2(acc[mt][n][2], acc[mt][n][3]);
    }
  }

  // epilogue 2: fused es/ed reduction. This warp's 64 cols lie in one head.
  int head = (bx*128 + wn*64) / DH;
  #pragma unroll
  for (int mt=0; mt<2; mt++){
    float ses0=0.f, sed0=0.f, ses1=0.f, sed1=0.f;
    #pragma unroll
    for (int n=0; n<8; n++){
      int c = bx*128 + wn*64 + n*8 + (lane&3)*2;
      float a0=asrc[c], a1=asrc[c+1], dd0=adst[c], dd1=adst[c+1];
      ses0 += acc[mt][n][0]*a0 + acc[mt][n][1]*a1;
      sed0 += acc[mt][n][0]*dd0 + acc[mt][n][1]*dd1;
      ses1 += acc[mt][n][2]*a0 + acc[mt][n][3]*a1;
      sed1 += acc[mt][n][2]*dd0 + acc[mt][n][3]*dd1;
    }
    #pragma unroll
    for (int o=1; o<=2; o<<=1){
      ses0 += __shfl_xor_sync(0xffffffffu, ses0, o);
      sed0 += __shfl_xor_sync(0xffffffffu, sed0, o);
      ses1 += __shfl_xor_sync(0xffffffffu, ses1, o);
      sed1 += __shfl_xor_sync(0xffffffffu, sed1, o);
    }
    if ((lane&3)==0){
      int rr = by*128 + wm*32 + mt*16 + (lane>>2);
      if (rr < MROWS){
        atomicAdd(&g_es[rr*NHEAD+head], ses0);
        atomicAdd(&g_ed[rr*NHEAD+head], sed0);
      }
      if (rr+8 < MROWS){
        atomicAdd(&g_es[(rr+8)*NHEAD+head], ses1);
        atomicAdd(&g_ed[(rr+8)*NHEAD+head], sed1);
      }
    }
  }
}

// 8 static in-edges for big node j (0..3 = label j, 4..7 = image j-4)
__device__ __forceinline__ int static_src(int j,int s){
  if (j<LLn){
    if (s<4) return TT+LLn+s;
    if (s<7){ int p=s-4; if(p>=j)p++; return TT+p; }
    return TT+j;
  } else {
    int jj=j-LLn;
    if (s<4) return TT+s;
    if (s<7){ int p=s-4; if(p>=jj)p++; return TT+LLn+p; }
    return TT+LLn+jj;
  }
}

// ---------------- big-node softmax max & sumexp (and zero agg) ----------------
__global__ void k_ms(){
  int b = blockIdx.x>>3, j = blockIdx.x&7;
  int tid = threadIdx.x;
  int jj = (j<LLn)? j : j-LLn;
  int dst = (j<LLn)? (TT+j) : (TT+LLn+jj);
  for (int c=tid;c<HH;c+=256) g_agg[blockIdx.x*HH+c]=0.f;
  float edv[4];
  #pragma unroll
  for (int h=0;h<4;h++) edv[h]=g_ed[(size_t)(b*NN+dst)*NHEAD+h];
  const int* minA = (j<LLn)? (g_minL+b*TT) : (g_minI+b*TT);
  float mx[4]={-3.4e38f,-3.4e38f,-3.4e38f,-3.4e38f};
  for (int t=tid;t<TT;t+=256){
    if (minA[t]!=jj){
      const float* e = g_es + (size_t)(b*NN+t)*NHEAD;
      #pragma unroll
      for (int h=0;h<4;h++) mx[h]=fmaxf(mx[h], lrelu(e[h]+edv[h]));
    }
  }
  if (tid==0){
    #pragma unroll
    for (int s=0;s<8;s++){
      int sr = static_src(j,s);
      const float* e = g_es + (size_t)(b*NN+sr)*NHEAD;
      #pragma unroll
      for (int h=0;h<4;h++) mx[h]=fmaxf(mx[h], lrelu(e[h]+edv[h]));
    }
  }
  __shared__ float red[256][4];
  #pragma unroll
  for (int h=0;h<4;h++) red[tid][h]=mx[h];
  __syncthreads();
  for (int st=128;st>0;st>>=1){
    if (tid<st){
      #pragma unroll
      for (int h=0;h<4;h++) red[tid][h]=fmaxf(red[tid][h],red[tid+st][h]);
    }
    __syncthreads();
  }
  float mv[4];
  #pragma unroll
  for (int h=0;h<4;h++) mv[h]=red[0][h];
  __syncthreads();
  float sm[4]={0.f,0.f,0.f,0.f};
  for (int t=tid;t<TT;t+=256){
    if (minA[t]!=jj){
      const float* e = g_es + (size_t)(b*NN+t)*NHEAD;
      #pragma unroll
      for (int h=0;h<4;h++) sm[h] += __expf(lrelu(e[h]+edv[h])-mv[h]);
    }
  }
  if (tid==0){
    #pragma unroll
    for (int s=0;s<8;s++){
      int sr = static_src(j,s);
      const float* e = g_es + (size_t)(b*NN+sr)*NHEAD;
      #pragma unroll
      for (int h=0;h<4;h++) sm[h] += __expf(lrelu(e[h]+edv[h])-mv[h]);
    }
  }
  #pragma unroll
  for (int h=0;h<4;h++) red[tid][h]=sm[h];
  __syncthreads();
  for (int st=128;st>0;st>>=1){
    if (tid<st){
      #pragma unroll
      for (int h=0;h<4;h++) red[tid][h]+=red[tid+st][h];
    }
    __syncthreads();
  }
  if (tid<4){
    g_m[(b*8+j)*NHEAD+tid]=mv[tid];
    g_s[(b*8+j)*NHEAD+tid]=red[0][tid];
  }
}

// ---------------- big-node weighted aggregation (all 8 j per block, alpha inline) ----------------
__global__ void k_agg(){
  int b  = blockIdx.x >> 5;
  int sp = blockIdx.x & 31;
  int tid = threadIdx.x;
  int t0 = sp*32;
  __shared__ float sal[32][8][4];
  #pragma unroll
  for (int q=0;q<4;q++){
    int idx = tid + q*256;          // 0..1023
    int tl = idx >> 5;
    int j  = (idx >> 2) & 7;
    int h  = idx & 3;
    int jj = (j<LLn)? j : j-LLn;
    int dst = (j<LLn)? (TT+j) : (TT+LLn+jj);
    int t = t0 + tl;
    int excl = (j<LLn)? (g_minL[b*TT+t]==jj) : (g_minI[b*TT+t]==jj);
    float al = 0.f;
    if (!excl){
      float e = lrelu(g_es[(size_t)(b*NN+t)*NHEAD+h] + g_ed[(size_t)(b*NN+dst)*NHEAD+h]);
      al = __expf(e - g_m[(b*8+j)*NHEAD+h]) / g_s[(b*8+j)*NHEAD+h];
    }
    sal[tl][j][h] = al;
  }
  __syncthreads();
  int c0=tid, c1=tid+256, c2=tid+512;
  int h0=c0/DH, h1=c1/DH, h2=c2/DH;
  float a0[8], a1[8], a2[8];
  #pragma unroll
  for (int j=0;j<8;j++){ a0[j]=0.f; a1[j]=0.f; a2[j]=0.f; }
  for (int tl=0; tl<32; tl++){
    const float* hr = g_hw + (size_t)(b*NN + t0+tl)*HH;
    float v0=hr[c0], v1=hr[c1], v2=hr[c2];
    #pragma unroll
    for (int j=0;j<8;j++){
      a0[j] += sal[tl][j][h0]*v0;
      a1[j] += sal[tl][j][h1]*v1;
      a2[j] += sal[tl][j][h2]*v2;
    }
  }
  #pragma unroll
  for (int j=0;j<8;j++){
    atomicAdd(&g_agg[(b*8+j)*HH+c0], a0[j]);
    atomicAdd(&g_agg[(b*8+j)*HH+c1], a1[j]);
    atomicAdd(&g_agg[(b*8+j)*HH+c2], a2[j]);
  }
}

// ---------------- big-node epilogue: static edges + bias+relu+residual+LN (+conv) ----------------
__global__ void k_big(const float* __restrict__ bias,const float* __restrict__ lng,
                      const float* __restrict__ lnb){
  int b = blockIdx.x>>3, j = blockIdx.x&7;
  int jj = (j<LLn)? j : j-LLn;
  int node = (j<LLn)? (TT+j) : (TT+LLn+jj);
  int tid = threadIdx.x;
  __shared__ float sal[8][4];
  __shared__ int ssrc[8];
  if (tid<32){
    int s=tid>>2, h=tid&3;
    int sr = static_src(j,s);
    if (h==0) ssrc[s]=sr;
    float e = lrelu(g_es[(size_t)(b*NN+sr)*NHEAD+h] + g_ed[(size_t)(b*NN+node)*NHEAD+h]);
    sal[s][h] = __expf(e - g_m[(b*8+j)*NHEAD+h]) / g_s[(b*8+j)*NHEAD+h];
  }
  __syncthreads();
  size_t row = (size_t)(b*NN+node)*HH;
  float v[3]; float s=0.f, sq=0.f;
  #pragma unroll
  for (int r=0;r<3;r++){
    int c = tid + 256*r;
    int hd = c/DH;
    float o = g_agg[(b*8+j)*HH+c];
    #pragma unroll
    for (int e=0;e<8;e++)
      o += sal[e][hd] * g_hw[(size_t)(b*NN+ssrc[e])*HH + c];
    o = fmaxf(o + bias[c], 0.f);
    float y = o + g_h[row+c];
    v[r]=y; s+=y; sq+=y*y;
  }
  __shared__ float rs[256], rq[256];
  rs[tid]=s; rq[tid]=sq; __syncthreads();
  for (int st=128;st>0;st>>=1){
    if (tid<st){ rs[tid]+=rs[tid+st]; rq[tid]+=rq[tid+st]; }
    __syncthreads();
  }
  float mu = rs[0]*(1.f/HH);
  float var = rq[0]*(1.f/HH) - mu*mu;
  float rstd = rsqrtf(var + 1e-5f);
  #pragma unroll
  for (int r=0;r<3;r++){
    int c = tid + 256*r;
    float y = (v[r]-mu)*rstd*lng[c] + lnb[c];
    g_h[row+c] = y;
    __nv_bfloat16 hi = __float2bfloat16(y);
    g_hh[row+c] = hi;
    g_hl[row+c] = __float2bfloat16(y - __bfloat162float(hi));
  }
}

// ---------------- text-node: full fused attention + epilogue (+conv or ->out) ----------------
__global__ void k_text(const float* __restrict__ bias,const float* __restrict__ lng,
                       const float* __restrict__ lnb, float* __restrict__ outp, int last){
  int bt = blockIdx.x;
  int b = bt/TT, t = bt%TT;
  int tid = threadIdx.x;
  __shared__ int ssrc[9];
  __shared__ int snum;
  __shared__ float sal[9][4];
  if (tid==0){
    int n=0;
    ssrc[n++]=t;
    if (t>0)    ssrc[n++]=t-1;
    if (t<TT-1) ssrc[n++]=t+1;
    int ml=g_minL[bt], mi=g_minI[bt];
    #pragma unroll
    for (int j2=0;j2<4;j2++) if (j2!=ml) ssrc[n++]=TT+j2;
    #pragma unroll
    for (int j2=0;j2<4;j2++) if (j2!=mi) ssrc[n++]=TT+LLn+j2;
    snum=n;
  }
  __syncthreads();
  int ns = snum;
  if (tid<4){
    float ed = g_ed[(size_t)(b*NN+t)*NHEAD + tid];
    float ev[9]; float mxv=-3.4e38f;
    for (int e=0;e<ns;e++){
      float x = lrelu(g_es[(size_t)(b*NN+ssrc[e])*NHEAD + tid] + ed);
      ev[e]=x; mxv=fmaxf(mxv,x);
    }
    float sm=0.f;
    for (int e=0;e<ns;e++){ float w=__expf(ev[e]-mxv); ev[e]=w; sm+=w; }
    float inv = 1.f/sm;
    for (int e=0;e<ns;e++) sal[e][tid]=ev[e]*inv;
  }
  __syncthreads();
  size_t row = (size_t)(b*NN+t)*HH;
  float v[3]; float s=0.f, sq=0.f;
  #pragma unroll
  for (int r=0;r<3;r++){
    int c = tid + 256*r;
    int hd = c/DH;
    float a = 0.f;
    for (int e=0;e<ns;e++)
      a += sal[e][hd] * g_hw[(size_t)(b*NN+ssrc[e])*HH + c];
    float o = fmaxf(a + bias[c], 0.f);
    float y = o + g_h[row+c];
    v[r]=y; s+=y; sq+=y*y;
  }
  __shared__ float rs[256], rq[256];
  rs[tid]=s; rq[tid]=sq; __syncthreads();
  for (int st=128;st>0;st>>=1){
    if (tid<st){ rs[tid]+=rs[tid+st]; rq[tid]+=rq[tid+st]; }
    __syncthreads();
  }
  float mu = rs[0]*(1.f/HH);
  float var = rq[0]*(1.f/HH) - mu*mu;
  float rstd = rsqrtf(var + 1e-5f);
  if (last){
    float* od = outp + ((size_t)b*TT + t)*HH;
    #pragma unroll
    for (int r=0;r<3;r++){
      int c = tid + 256*r;
      od[c] = (v[r]-mu)*rstd*lng[c] + lnb[c];
    }
  } else {
    #pragma unroll
    for (int r=0;r<3;r++){
      int c = tid + 256*r;
      float y = (v[r]-mu)*rstd*lng[c] + lnb[c];
      g_h[row+c] = y;
      __nv_bfloat16 hi = __float2bfloat16(y);
      g_hh[row+c] = hi;
      g_hl[row+c] = __float2bfloat16(y - __bfloat162float(hi));
    }
  }
}

extern "C" void kernel_launch(void* const* d_in, const int* in_sizes, int n_in,
                              void* d_out, int out_size) {
  const float* text = (const float*)d_in[0];
  const float* lab  = (const float*)d_in[1];
  const float* img  = (const float*)d_in[2];
  const float* W    = (const float*)d_in[3];
  const float* asrc = (const float*)d_in[4];
  const float* adst = (const float*)d_in[5];
  const float* bias = (const float*)d_in[6];
  const float* lng  = (const float*)d_in[7];
  const float* lnb  = (const float*)d_in[8];
  float* out = (float*)d_out;

  cudaFuncSetAttribute(k_gemm_mma, cudaFuncAttributeMaxDynamicSharedMemorySize, GEMM_SMEM);

  k_pack<<<(MROWS*HH+255)/256, 256>>>(text, lab, img);
  k_cvtW<<<dim3(24,24,3), dim3(32,32)>>>(W);
  k_norm<<<BB*8, 128>>>(lab, img);
  k_topk<<<BB*TT, 128>>>(text, lab, img);

  for (int l=0; l<NLAY; l++){
    int last = (l == NLAY-1);
    k_zero<<<(MROWS*NHEAD+255)/256, 256>>>();
    k_gemm_mma<<<dim3(6,65), 256, GEMM_SMEM>>>(l, asrc + l*NHEAD*DH, adst + l*NHEAD*DH);
    if (!last){
      k_ms<<<BB*8, 256>>>();
      k_agg<<<BB*32, 256>>>();
      k_big<<<BB*8, 256>>>(bias + l*HH, lng + l*HH, lnb + l*HH);
    }
    k_text<<<BB*TT, 256>>>(bias + l*HH, lng + l*HH, lnb + l*HH, out, last);
  }
}